// round 1
// baseline (speedup 1.0000x reference)
#include <cuda_runtime.h>
#include <cuda_bf16.h>
#include <cstdint>

// Problem constants
#define Bz 8
#define Tz 1024
#define Vz 8192
#define Dz 1024
#define Hz 16
#define HDz 64
#define Lz 6
#define NT (Bz*Tz)          // 8192 tokens
#define THREED (3*Dz)       // 3072

// ---------------- scratch (static device memory; allocation-free) ----------------
__device__ float g_embT[(size_t)Vz * Dz];     // 32 MB  W_emb transposed [V,D]
__device__ float g_x[(size_t)NT * Dz];        // 32 MB  residual stream
__device__ float g_h[(size_t)NT * Dz];        // 32 MB  layernorm output
__device__ float g_qkv[(size_t)NT * THREED];  // 96 MB
__device__ float g_nll[NT];
__device__ int   g_tok[NT];

// ---------------- 1) extract token ids from dense one-hot ----------------
__global__ void find_tokens_kernel(const float* __restrict__ idx, int* __restrict__ tok) {
    int n = blockIdx.x;
    const float* row = idx + (size_t)n * Vz;
    for (int i = threadIdx.x; i < Vz; i += blockDim.x) {
        if (row[i] > 0.5f) tok[n] = i;
    }
}

// ---------------- 2) transpose W_emb [D,V] -> [V,D] ----------------
__global__ void transpose_kernel(const float* __restrict__ in, float* __restrict__ out) {
    __shared__ float tile[32][33];
    int x = blockIdx.x * 32 + threadIdx.x;   // V dim
    int y0 = blockIdx.y * 32;                // D dim
    #pragma unroll
    for (int j = threadIdx.y; j < 32; j += 8)
        tile[j][threadIdx.x] = in[(size_t)(y0 + j) * Vz + x];
    __syncthreads();
    int xo = blockIdx.y * 32 + threadIdx.x;  // D dim (output inner)
    int yo0 = blockIdx.x * 32;               // V dim
    #pragma unroll
    for (int j = threadIdx.y; j < 32; j += 8)
        out[(size_t)(yo0 + j) * Dz + xo] = tile[threadIdx.x][j];
}

// ---------------- 3) embedding gather ----------------
__global__ void embed_kernel(const float* __restrict__ embT, const int* __restrict__ tok,
                             float* __restrict__ x) {
    int n = blockIdx.x;
    int t = tok[n];
    const float4* src = (const float4*)(embT + (size_t)t * Dz);
    float4* dst = (float4*)(x + (size_t)n * Dz);
    dst[threadIdx.x] = src[threadIdx.x];   // 256 threads * 4 = 1024
}

// ---------------- 4) layernorm (no affine), row of 1024 ----------------
__global__ void layernorm_kernel(const float* __restrict__ in, float* __restrict__ out) {
    int n = blockIdx.x;
    const float4* row = (const float4*)(in + (size_t)n * Dz);
    float4 v = row[threadIdx.x];
    float s  = v.x + v.y + v.z + v.w;
    float ss = v.x*v.x + v.y*v.y + v.z*v.z + v.w*v.w;
    #pragma unroll
    for (int off = 16; off >= 1; off >>= 1) {
        s  += __shfl_xor_sync(0xffffffffu, s,  off);
        ss += __shfl_xor_sync(0xffffffffu, ss, off);
    }
    __shared__ float sm[8], sm2[8];
    int wid = threadIdx.x >> 5, lane = threadIdx.x & 31;
    if (lane == 0) { sm[wid] = s; sm2[wid] = ss; }
    __syncthreads();
    __shared__ float s_mu, s_rstd;
    if (threadIdx.x == 0) {
        float ts = 0.f, tss = 0.f;
        #pragma unroll
        for (int i = 0; i < 8; i++) { ts += sm[i]; tss += sm2[i]; }
        float mu = ts / (float)Dz;
        float var = tss / (float)Dz - mu * mu;
        s_mu = mu;
        s_rstd = rsqrtf(var + 1e-5f);
    }
    __syncthreads();
    float mu = s_mu, rstd = s_rstd;
    float4 o;
    o.x = (v.x - mu) * rstd; o.y = (v.y - mu) * rstd;
    o.z = (v.z - mu) * rstd; o.w = (v.w - mu) * rstd;
    ((float4*)(out + (size_t)n * Dz))[threadIdx.x] = o;
}

// ---------------- 5) SGEMM NT: C[M,N] = A[M,K] * B[N,K]^T  (all dims %128==0, K%8==0) ---
#define GBM 128
#define GBN 128
#define GBK 8
__global__ __launch_bounds__(256, 2)
void sgemm_nt_kernel(const float* __restrict__ A, const float* __restrict__ B,
                     float* __restrict__ C, int M, int N, int K) {
    __shared__ float As[GBK][GBM];
    __shared__ float Bs[GBK][GBN];
    int bm = blockIdx.y * GBM;
    int bn = blockIdx.x * GBN;
    int tid = threadIdx.x;
    int tr = tid >> 4;        // 0..15
    int tc = tid & 15;        // 0..15
    int lr = tid >> 1;        // 0..127 load row
    int lk = (tid & 1) * 4;   // 0 or 4

    float acc[8][8];
    #pragma unroll
    for (int i = 0; i < 8; i++)
        #pragma unroll
        for (int j = 0; j < 8; j++) acc[i][j] = 0.f;

    const float* Aptr = A + (size_t)(bm + lr) * K + lk;
    const float* Bptr = B + (size_t)(bn + lr) * K + lk;

    for (int k0 = 0; k0 < K; k0 += GBK) {
        float4 a4 = *(const float4*)(Aptr + k0);
        float4 b4 = *(const float4*)(Bptr + k0);
        As[lk+0][lr] = a4.x; As[lk+1][lr] = a4.y; As[lk+2][lr] = a4.z; As[lk+3][lr] = a4.w;
        Bs[lk+0][lr] = b4.x; Bs[lk+1][lr] = b4.y; Bs[lk+2][lr] = b4.z; Bs[lk+3][lr] = b4.w;
        __syncthreads();
        #pragma unroll
        for (int k = 0; k < GBK; k++) {
            float4 af0 = *(const float4*)&As[k][tr * 8];
            float4 af1 = *(const float4*)&As[k][tr * 8 + 4];
            float4 bf0 = *(const float4*)&Bs[k][tc * 8];
            float4 bf1 = *(const float4*)&Bs[k][tc * 8 + 4];
            float a[8] = {af0.x, af0.y, af0.z, af0.w, af1.x, af1.y, af1.z, af1.w};
            float b[8] = {bf0.x, bf0.y, bf0.z, bf0.w, bf1.x, bf1.y, bf1.z, bf1.w};
            #pragma unroll
            for (int i = 0; i < 8; i++)
                #pragma unroll
                for (int j = 0; j < 8; j++)
                    acc[i][j] += a[i] * b[j];
        }
        __syncthreads();
    }
    #pragma unroll
    for (int i = 0; i < 8; i++) {
        float* cp = C + (size_t)(bm + tr * 8 + i) * N + bn + tc * 8;
        float4 c0 = {acc[i][0], acc[i][1], acc[i][2], acc[i][3]};
        float4 c1 = {acc[i][4], acc[i][5], acc[i][6], acc[i][7]};
        ((float4*)cp)[0] = c0;
        ((float4*)cp)[1] = c1;
    }
}

// ---------------- 6) fused causal flash attention + residual add ----------------
// grid: (T/64, B*H), 128 threads. Q tile 64 rows, KV tiles 32 rows, HD=64.
__global__ __launch_bounds__(128)
void flash_attn_kernel(const float* __restrict__ qkv, float* __restrict__ x) {
    int qt = blockIdx.x;
    int bh = blockIdx.y;
    int b = bh / Hz, h = bh % Hz;
    int tid = threadIdx.x;
    int tx = tid & 15;        // key/hd column group
    int ty = tid >> 4;        // 0..7 row group (8 rows each)

    __shared__ float Qs[64][64];    // 16 KB
    __shared__ float KP[2112];      // K tile as [32][65] OR P tile as [64][33]
    __shared__ float Vs[32][64];    // 8 KB

    const int q0 = qt * 64;
    const float* base = qkv + (size_t)b * Tz * THREED;
    const int hc = h * HDz;

    // load Q tile, pre-scaled by 1/sqrt(HD)
    for (int i = tid; i < 64 * 64; i += 128) {
        int r = i >> 6, c = i & 63;
        Qs[r][c] = base[(size_t)(q0 + r) * THREED + hc + c] * 0.125f;
    }

    float m[8], l[8], O[8][4];
    #pragma unroll
    for (int i = 0; i < 8; i++) {
        m[i] = -1e30f; l[i] = 0.f;
        #pragma unroll
        for (int c = 0; c < 4; c++) O[i][c] = 0.f;
    }

    const int nkv = (q0 + 64) / 32;
    for (int j = 0; j < nkv; j++) {
        int k0 = j * 32;
        __syncthreads();   // previous P/V consumers done
        for (int i = tid; i < 32 * 64; i += 128) {
            int r = i >> 6, c = i & 63;
            const float* kr = base + (size_t)(k0 + r) * THREED;
            KP[r * 65 + c] = kr[Dz + hc + c];       // K section
            Vs[r][c]       = kr[2 * Dz + hc + c];   // V section
        }
        __syncthreads();

        // S[8 rows][2 cols]
        float S[8][2];
        #pragma unroll
        for (int i = 0; i < 8; i++) { S[i][0] = 0.f; S[i][1] = 0.f; }
        #pragma unroll 4
        for (int k = 0; k < 64; k++) {
            float kk0 = KP[(tx * 2 + 0) * 65 + k];
            float kk1 = KP[(tx * 2 + 1) * 65 + k];
            #pragma unroll
            for (int i = 0; i < 8; i++) {
                float qv = Qs[ty * 8 + i][k];
                S[i][0] += qv * kk0;
                S[i][1] += qv * kk1;
            }
        }
        // causal mask (only last two tiles of each q-tile can be partial)
        if (k0 + 31 > q0) {
            #pragma unroll
            for (int i = 0; i < 8; i++) {
                int r = q0 + ty * 8 + i;
                if (k0 + tx * 2 + 0 > r) S[i][0] = -1e30f;
                if (k0 + tx * 2 + 1 > r) S[i][1] = -1e30f;
            }
        }
        // online softmax update
        float P[8][2];
        #pragma unroll
        for (int i = 0; i < 8; i++) {
            float rmax = fmaxf(S[i][0], S[i][1]);
            #pragma unroll
            for (int off = 8; off >= 1; off >>= 1)
                rmax = fmaxf(rmax, __shfl_xor_sync(0xffffffffu, rmax, off));
            float mnew = fmaxf(m[i], rmax);
            float scale = __expf(m[i] - mnew);
            m[i] = mnew;
            P[i][0] = __expf(S[i][0] - mnew);
            P[i][1] = __expf(S[i][1] - mnew);
            float rsum = P[i][0] + P[i][1];
            #pragma unroll
            for (int off = 8; off >= 1; off >>= 1)
                rsum += __shfl_xor_sync(0xffffffffu, rsum, off);
            l[i] = l[i] * scale + rsum;
            #pragma unroll
            for (int c = 0; c < 4; c++) O[i][c] *= scale;
        }
        __syncthreads();   // all K reads done; reuse KP as P [64][33]
        #pragma unroll
        for (int i = 0; i < 8; i++) {
            KP[(ty * 8 + i) * 33 + tx * 2 + 0] = P[i][0];
            KP[(ty * 8 + i) * 33 + tx * 2 + 1] = P[i][1];
        }
        __syncthreads();
        // O += P * V
        #pragma unroll 4
        for (int kk = 0; kk < 32; kk++) {
            float4 vv = *(const float4*)&Vs[kk][tx * 4];
            #pragma unroll
            for (int i = 0; i < 8; i++) {
                float p = KP[(ty * 8 + i) * 33 + kk];
                O[i][0] += p * vv.x;
                O[i][1] += p * vv.y;
                O[i][2] += p * vv.z;
                O[i][3] += p * vv.w;
            }
        }
    }
    // epilogue: normalize and residual-add into x
    #pragma unroll
    for (int i = 0; i < 8; i++) {
        float inv = 1.0f / l[i];
        float* xp = x + (size_t)(b * Tz + q0 + ty * 8 + i) * Dz + hc + tx * 4;
        float4 old = *(float4*)xp;
        old.x += O[i][0] * inv;
        old.y += O[i][1] * inv;
        old.z += O[i][2] * inv;
        old.w += O[i][3] * inv;
        *(float4*)xp = old;
    }
}

// ---------------- 7) per-row NLL: lse(row) - row[target] ----------------
__device__ __forceinline__ void lse_combine(float& m, float& s, float m2, float s2) {
    float M = fmaxf(m, m2);
    s = s * __expf(m - M) + s2 * __expf(m2 - M);
    m = M;
}
__global__ void row_nll_kernel(const float* __restrict__ logits, const int* __restrict__ targets,
                               float* __restrict__ nll) {
    int n = blockIdx.x;
    const float* row = logits + (size_t)n * Vz;
    float m = -1e30f, s = 0.f;
    for (int i = threadIdx.x; i < Vz; i += 256) {
        float v = row[i];
        float M = fmaxf(m, v);
        s = s * __expf(m - M) + __expf(v - M);
        m = M;
    }
    #pragma unroll
    for (int off = 16; off >= 1; off >>= 1) {
        float m2 = __shfl_xor_sync(0xffffffffu, m, off);
        float s2 = __shfl_xor_sync(0xffffffffu, s, off);
        lse_combine(m, s, m2, s2);
    }
    __shared__ float sm[8], ssum[8];
    int wid = threadIdx.x >> 5, lane = threadIdx.x & 31;
    if (lane == 0) { sm[wid] = m; ssum[wid] = s; }
    __syncthreads();
    if (threadIdx.x == 0) {
        float M = sm[0], S = ssum[0];
        #pragma unroll
        for (int i = 1; i < 8; i++) lse_combine(M, S, sm[i], ssum[i]);
        float lse = M + logf(S);
        nll[n] = lse - row[targets[n]];
    }
}

// ---------------- 8) mean-reduce loss ----------------
__global__ void loss_mean_kernel(const float* __restrict__ nll, float* __restrict__ out,
                                 long long out_size) {
    float s = 0.f;
    for (int i = threadIdx.x; i < NT; i += 256) s += nll[i];
    #pragma unroll
    for (int off = 16; off >= 1; off >>= 1) s += __shfl_xor_sync(0xffffffffu, s, off);
    __shared__ float sm[8];
    int wid = threadIdx.x >> 5, lane = threadIdx.x & 31;
    if (lane == 0) sm[wid] = s;
    __syncthreads();
    if (threadIdx.x == 0) {
        float t = 0.f;
        #pragma unroll
        for (int i = 0; i < 8; i++) t += sm[i];
        const long long NTV = (long long)NT * Vz;
        if (out_size > NTV) out[NTV] = t / (float)NT;
    }
}

// ---------------- launch ----------------
extern "C" void kernel_launch(void* const* d_in, const int* in_sizes, int n_in,
                              void* d_out, int out_size) {
    const float* idx     = (const float*)d_in[0];
    const int*   targets = (const int*)d_in[1];
    const float* W_emb   = (const float*)d_in[2];
    const float* W_attn  = (const float*)d_in[3];
    const float* W_out   = (const float*)d_in[4];
    float* out = (float*)d_out;

    void* p;
    cudaGetSymbolAddress(&p, g_embT); float* embT = (float*)p;
    cudaGetSymbolAddress(&p, g_x);    float* x    = (float*)p;
    cudaGetSymbolAddress(&p, g_h);    float* h    = (float*)p;
    cudaGetSymbolAddress(&p, g_qkv);  float* qkv  = (float*)p;
    cudaGetSymbolAddress(&p, g_nll);  float* nll  = (float*)p;
    cudaGetSymbolAddress(&p, g_tok);  int*   tok  = (int*)p;

    find_tokens_kernel<<<NT, 256>>>(idx, tok);
    transpose_kernel<<<dim3(Vz / 32, Dz / 32), dim3(32, 8)>>>(W_emb, embT);
    embed_kernel<<<NT, 256>>>(embT, tok, x);

    for (int l = 0; l < Lz; l++) {
        layernorm_kernel<<<NT, 256>>>(x, h);
        sgemm_nt_kernel<<<dim3(THREED / GBN, NT / GBM), 256>>>(
            h, W_attn + (size_t)l * THREED * Dz, qkv, NT, THREED, Dz);
        flash_attn_kernel<<<dim3(Tz / 64, Bz * Hz), 128>>>(qkv, x);
    }

    layernorm_kernel<<<NT, 256>>>(x, h);
    sgemm_nt_kernel<<<dim3(Vz / GBN, NT / GBM), 256>>>(h, W_out, out, NT, Vz, Dz);

    row_nll_kernel<<<NT, 256>>>(out, targets, nll);
    loss_mean_kernel<<<1, 256>>>(nll, out, (long long)out_size);
}

// round 3
// speedup vs baseline: 1.8450x; 1.8450x over previous
#include <cuda_runtime.h>
#include <cuda_bf16.h>
#include <cstdint>

// Problem constants
#define Bz 8
#define Tz 1024
#define Vz 8192
#define Dz 1024
#define Hz 16
#define HDz 64
#define Lz 6
#define NT (Bz*Tz)          // 8192 tokens
#define THREED (3*Dz)       // 3072

// ---------------- scratch (static device memory; allocation-free) ----------------
__device__ float g_embT[(size_t)Vz * Dz];       // 32 MB  W_emb transposed [V,D]
__device__ float g_x[(size_t)NT * Dz];          // 32 MB  residual stream
__device__ float g_h[(size_t)NT * Dz];          // 32 MB  layernorm output (tf32-rounded)
__device__ float g_qkv[(size_t)NT * THREED];    // 96 MB
__device__ float g_wattn_r[(size_t)Lz * THREED * Dz];  // 75 MB tf32-rounded W_attn
__device__ float g_wout_r[(size_t)Vz * Dz];     // 32 MB tf32-rounded W_out
__device__ float g_nll[NT];
__device__ int   g_tok[NT];

// cvt.rna.tf32.f32 needs a .b32 destination register
__device__ __forceinline__ float tf32_round(float x) {
    uint32_t r;
    asm("cvt.rna.tf32.f32 %0, %1;\n" : "=r"(r) : "f"(x));
    return __uint_as_float(r);
}

// ---------------- 1) extract token ids from dense one-hot ----------------
__global__ void find_tokens_kernel(const float* __restrict__ idx, int* __restrict__ tok) {
    int n = blockIdx.x;
    const float* row = idx + (size_t)n * Vz;
    for (int i = threadIdx.x; i < Vz; i += blockDim.x) {
        if (row[i] > 0.5f) tok[n] = i;
    }
}

// ---------------- 2) transpose W_emb [D,V] -> [V,D] ----------------
__global__ void transpose_kernel(const float* __restrict__ in, float* __restrict__ out) {
    __shared__ float tile[32][33];
    int x = blockIdx.x * 32 + threadIdx.x;   // V dim
    int y0 = blockIdx.y * 32;                // D dim
    #pragma unroll
    for (int j = threadIdx.y; j < 32; j += 8)
        tile[j][threadIdx.x] = in[(size_t)(y0 + j) * Vz + x];
    __syncthreads();
    int xo = blockIdx.y * 32 + threadIdx.x;  // D dim (output inner)
    int yo0 = blockIdx.x * 32;               // V dim
    #pragma unroll
    for (int j = threadIdx.y; j < 32; j += 8)
        out[(size_t)(yo0 + j) * Dz + xo] = tile[threadIdx.x][j];
}

// ---------------- 3) embedding gather ----------------
__global__ void embed_kernel(const float* __restrict__ embT, const int* __restrict__ tok,
                             float* __restrict__ x) {
    int n = blockIdx.x;
    int t = tok[n];
    const float4* src = (const float4*)(embT + (size_t)t * Dz);
    float4* dst = (float4*)(x + (size_t)n * Dz);
    dst[threadIdx.x] = src[threadIdx.x];   // 256 threads * 4 = 1024
}

// ---------------- 3b) tf32-round a buffer (weights prepass) ----------------
__global__ void round_tf32_kernel(const float* __restrict__ in, float* __restrict__ out,
                                  long long n4) {
    long long i = (long long)blockIdx.x * blockDim.x + threadIdx.x;
    long long stride = (long long)gridDim.x * blockDim.x;
    for (; i < n4; i += stride) {
        float4 v = ((const float4*)in)[i];
        v.x = tf32_round(v.x); v.y = tf32_round(v.y);
        v.z = tf32_round(v.z); v.w = tf32_round(v.w);
        ((float4*)out)[i] = v;
    }
}

// ---------------- 4) layernorm (no affine), row of 1024, tf32-rounded output ---
__global__ void layernorm_kernel(const float* __restrict__ in, float* __restrict__ out) {
    int n = blockIdx.x;
    const float4* row = (const float4*)(in + (size_t)n * Dz);
    float4 v = row[threadIdx.x];
    float s  = v.x + v.y + v.z + v.w;
    float ss = v.x*v.x + v.y*v.y + v.z*v.z + v.w*v.w;
    #pragma unroll
    for (int off = 16; off >= 1; off >>= 1) {
        s  += __shfl_xor_sync(0xffffffffu, s,  off);
        ss += __shfl_xor_sync(0xffffffffu, ss, off);
    }
    __shared__ float sm[8], sm2[8];
    int wid = threadIdx.x >> 5, lane = threadIdx.x & 31;
    if (lane == 0) { sm[wid] = s; sm2[wid] = ss; }
    __syncthreads();
    __shared__ float s_mu, s_rstd;
    if (threadIdx.x == 0) {
        float ts = 0.f, tss = 0.f;
        #pragma unroll
        for (int i = 0; i < 8; i++) { ts += sm[i]; tss += sm2[i]; }
        float mu = ts / (float)Dz;
        float var = tss / (float)Dz - mu * mu;
        s_mu = mu;
        s_rstd = rsqrtf(var + 1e-5f);
    }
    __syncthreads();
    float mu = s_mu, rstd = s_rstd;
    float4 o;
    o.x = tf32_round((v.x - mu) * rstd); o.y = tf32_round((v.y - mu) * rstd);
    o.z = tf32_round((v.z - mu) * rstd); o.w = tf32_round((v.w - mu) * rstd);
    ((float4*)(out + (size_t)n * Dz))[threadIdx.x] = o;
}

// ---------------- 5) TF32 tensor-core GEMM NT: C[M,N] = A[M,K] * B[N,K]^T ------
// CTA tile 128x128x16, 8 warps (4x2), warp tile 32x64, double-buffered cp.async.
// A, B already tf32-rounded. Dims: M%128==0, N%128==0, K%16==0.
#define BM 128
#define BN 128
#define BK 16
#define SST 20    // smem row stride (16 + 4 pad) -> conflict-free fragment reads

__device__ __forceinline__ void cp16(uint32_t dst, const float* src) {
    asm volatile("cp.async.ca.shared.global [%0], [%1], 16;\n" :: "r"(dst), "l"(src));
}

__global__ __launch_bounds__(256)
void tf32_gemm_nt(const float* __restrict__ A, const float* __restrict__ B,
                  float* __restrict__ C, int M, int N, int K) {
    __shared__ float As[2][BM * SST];
    __shared__ float Bs[2][BN * SST];

    const int bm = blockIdx.y * BM;
    const int bn = blockIdx.x * BN;
    const int tid = threadIdx.x;
    const int wid = tid >> 5, lane = tid & 31;
    const int wm = wid >> 1;      // 0..3
    const int wn = wid & 1;       // 0..1
    const int g  = lane >> 2;     // 0..7
    const int tg = lane & 3;      // 0..3

    // global->smem load mapping: 2 threads per row, 8 floats (2x16B) each
    const int lrow = tid >> 1;        // 0..127
    const int lseg = (tid & 1) * 8;   // 0 or 8

    const float* Ag = A + (size_t)(bm + lrow) * K + lseg;
    const float* Bg = B + (size_t)(bn + lrow) * K + lseg;
    uint32_t AsW[2], BsW[2];
    #pragma unroll
    for (int b = 0; b < 2; b++) {
        AsW[b] = (uint32_t)__cvta_generic_to_shared(&As[b][lrow * SST + lseg]);
        BsW[b] = (uint32_t)__cvta_generic_to_shared(&Bs[b][lrow * SST + lseg]);
    }

    float c[2][8][4];
    #pragma unroll
    for (int i = 0; i < 2; i++)
        #pragma unroll
        for (int j = 0; j < 8; j++)
            #pragma unroll
            for (int r = 0; r < 4; r++) c[i][j][r] = 0.f;

    const int ntiles = K / BK;

    // prologue: tile 0 -> buf 0
    cp16(AsW[0],     Ag);
    cp16(AsW[0]+16,  Ag + 4);
    cp16(BsW[0],     Bg);
    cp16(BsW[0]+16,  Bg + 4);
    asm volatile("cp.async.commit_group;\n");

    for (int kt = 0; kt < ntiles; kt++) {
        const int buf = kt & 1;
        if (kt + 1 < ntiles) {
            const float* a2 = Ag + (size_t)(kt + 1) * BK;
            const float* b2 = Bg + (size_t)(kt + 1) * BK;
            cp16(AsW[buf^1],    a2);
            cp16(AsW[buf^1]+16, a2 + 4);
            cp16(BsW[buf^1],    b2);
            cp16(BsW[buf^1]+16, b2 + 4);
            asm volatile("cp.async.commit_group;\n");
            asm volatile("cp.async.wait_group 1;\n");
        } else {
            asm volatile("cp.async.wait_group 0;\n");
        }
        __syncthreads();

        const float* pA = As[buf];
        const float* pB = Bs[buf];
        #pragma unroll
        for (int ks = 0; ks < 2; ks++) {
            const int kb = ks * 8;
            uint32_t a[2][4], b[8][2];
            #pragma unroll
            for (int i = 0; i < 2; i++) {
                const int mb = wm * 32 + i * 16;
                a[i][0] = __float_as_uint(pA[(mb + g    ) * SST + kb + tg    ]);
                a[i][1] = __float_as_uint(pA[(mb + g + 8) * SST + kb + tg    ]);
                a[i][2] = __float_as_uint(pA[(mb + g    ) * SST + kb + tg + 4]);
                a[i][3] = __float_as_uint(pA[(mb + g + 8) * SST + kb + tg + 4]);
            }
            #pragma unroll
            for (int j = 0; j < 8; j++) {
                const int nb = wn * 64 + j * 8;
                b[j][0] = __float_as_uint(pB[(nb + g) * SST + kb + tg    ]);
                b[j][1] = __float_as_uint(pB[(nb + g) * SST + kb + tg + 4]);
            }
            #pragma unroll
            for (int i = 0; i < 2; i++)
                #pragma unroll
                for (int j = 0; j < 8; j++) {
                    asm volatile(
                        "mma.sync.aligned.m16n8k8.row.col.f32.tf32.tf32.f32 "
                        "{%0,%1,%2,%3}, {%4,%5,%6,%7}, {%8,%9}, {%0,%1,%2,%3};\n"
                        : "+f"(c[i][j][0]), "+f"(c[i][j][1]),
                          "+f"(c[i][j][2]), "+f"(c[i][j][3])
                        : "r"(a[i][0]), "r"(a[i][1]), "r"(a[i][2]), "r"(a[i][3]),
                          "r"(b[j][0]), "r"(b[j][1]));
                }
        }
        __syncthreads();
    }

    // epilogue
    #pragma unroll
    for (int i = 0; i < 2; i++) {
        const int m0 = bm + wm * 32 + i * 16 + g;
        #pragma unroll
        for (int j = 0; j < 8; j++) {
            const int n0 = bn + wn * 64 + j * 8 + 2 * tg;
            float2 v0 = {c[i][j][0], c[i][j][1]};
            float2 v1 = {c[i][j][2], c[i][j][3]};
            *(float2*)(C + (size_t)m0 * N + n0)       = v0;
            *(float2*)(C + (size_t)(m0 + 8) * N + n0) = v1;
        }
    }
}

// ---------------- 6) fused causal flash attention + residual add ----------------
// grid: (T/64, B*H), 128 threads. Q tile 64 rows, KV tiles 32 rows, HD=64.
__global__ __launch_bounds__(128)
void flash_attn_kernel(const float* __restrict__ qkv, float* __restrict__ x) {
    int qt = blockIdx.x;
    int bh = blockIdx.y;
    int b = bh / Hz, h = bh % Hz;
    int tid = threadIdx.x;
    int tx = tid & 15;        // key/hd column group
    int ty = tid >> 4;        // 0..7 row group (8 rows each)

    __shared__ float Qs[64][64];    // 16 KB
    __shared__ float KP[2112];      // K tile as [32][65] OR P tile as [64][33]
    __shared__ float Vs[32][64];    // 8 KB

    const int q0 = qt * 64;
    const float* base = qkv + (size_t)b * Tz * THREED;
    const int hc = h * HDz;

    // load Q tile, pre-scaled by 1/sqrt(HD)
    for (int i = tid; i < 64 * 64; i += 128) {
        int r = i >> 6, c = i & 63;
        Qs[r][c] = base[(size_t)(q0 + r) * THREED + hc + c] * 0.125f;
    }

    float m[8], l[8], O[8][4];
    #pragma unroll
    for (int i = 0; i < 8; i++) {
        m[i] = -1e30f; l[i] = 0.f;
        #pragma unroll
        for (int c = 0; c < 4; c++) O[i][c] = 0.f;
    }

    const int nkv = (q0 + 64) / 32;
    for (int j = 0; j < nkv; j++) {
        int k0 = j * 32;
        __syncthreads();   // previous P/V consumers done
        for (int i = tid; i < 32 * 64; i += 128) {
            int r = i >> 6, c = i & 63;
            const float* kr = base + (size_t)(k0 + r) * THREED;
            KP[r * 65 + c] = kr[Dz + hc + c];       // K section
            Vs[r][c]       = kr[2 * Dz + hc + c];   // V section
        }
        __syncthreads();

        // S[8 rows][2 cols]
        float S[8][2];
        #pragma unroll
        for (int i = 0; i < 8; i++) { S[i][0] = 0.f; S[i][1] = 0.f; }
        #pragma unroll 4
        for (int k = 0; k < 64; k++) {
            float kk0 = KP[(tx * 2 + 0) * 65 + k];
            float kk1 = KP[(tx * 2 + 1) * 65 + k];
            #pragma unroll
            for (int i = 0; i < 8; i++) {
                float qv = Qs[ty * 8 + i][k];
                S[i][0] += qv * kk0;
                S[i][1] += qv * kk1;
            }
        }
        // causal mask (only last two tiles of each q-tile can be partial)
        if (k0 + 31 > q0) {
            #pragma unroll
            for (int i = 0; i < 8; i++) {
                int r = q0 + ty * 8 + i;
                if (k0 + tx * 2 + 0 > r) S[i][0] = -1e30f;
                if (k0 + tx * 2 + 1 > r) S[i][1] = -1e30f;
            }
        }
        // online softmax update
        float P[8][2];
        #pragma unroll
        for (int i = 0; i < 8; i++) {
            float rmax = fmaxf(S[i][0], S[i][1]);
            #pragma unroll
            for (int off = 8; off >= 1; off >>= 1)
                rmax = fmaxf(rmax, __shfl_xor_sync(0xffffffffu, rmax, off));
            float mnew = fmaxf(m[i], rmax);
            float scale = __expf(m[i] - mnew);
            m[i] = mnew;
            P[i][0] = __expf(S[i][0] - mnew);
            P[i][1] = __expf(S[i][1] - mnew);
            float rsum = P[i][0] + P[i][1];
            #pragma unroll
            for (int off = 8; off >= 1; off >>= 1)
                rsum += __shfl_xor_sync(0xffffffffu, rsum, off);
            l[i] = l[i] * scale + rsum;
            #pragma unroll
            for (int c = 0; c < 4; c++) O[i][c] *= scale;
        }
        __syncthreads();   // all K reads done; reuse KP as P [64][33]
        #pragma unroll
        for (int i = 0; i < 8; i++) {
            KP[(ty * 8 + i) * 33 + tx * 2 + 0] = P[i][0];
            KP[(ty * 8 + i) * 33 + tx * 2 + 1] = P[i][1];
        }
        __syncthreads();
        // O += P * V
        #pragma unroll 4
        for (int kk = 0; kk < 32; kk++) {
            float4 vv = *(const float4*)&Vs[kk][tx * 4];
            #pragma unroll
            for (int i = 0; i < 8; i++) {
                float p = KP[(ty * 8 + i) * 33 + kk];
                O[i][0] += p * vv.x;
                O[i][1] += p * vv.y;
                O[i][2] += p * vv.z;
                O[i][3] += p * vv.w;
            }
        }
    }
    // epilogue: normalize and residual-add into x
    #pragma unroll
    for (int i = 0; i < 8; i++) {
        float inv = 1.0f / l[i];
        float* xp = x + (size_t)(b * Tz + q0 + ty * 8 + i) * Dz + hc + tx * 4;
        float4 old = *(float4*)xp;
        old.x += O[i][0] * inv;
        old.y += O[i][1] * inv;
        old.z += O[i][2] * inv;
        old.w += O[i][3] * inv;
        *(float4*)xp = old;
    }
}

// ---------------- 7) per-row NLL: lse(row) - row[target] ----------------
__device__ __forceinline__ void lse_combine(float& m, float& s, float m2, float s2) {
    float M = fmaxf(m, m2);
    s = s * __expf(m - M) + s2 * __expf(m2 - M);
    m = M;
}
__global__ void row_nll_kernel(const float* __restrict__ logits, const int* __restrict__ targets,
                               float* __restrict__ nll) {
    int n = blockIdx.x;
    const float* row = logits + (size_t)n * Vz;
    float m = -1e30f, s = 0.f;
    for (int i = threadIdx.x; i < Vz; i += 256) {
        float v = row[i];
        float M = fmaxf(m, v);
        s = s * __expf(m - M) + __expf(v - M);
        m = M;
    }
    #pragma unroll
    for (int off = 16; off >= 1; off >>= 1) {
        float m2 = __shfl_xor_sync(0xffffffffu, m, off);
        float s2 = __shfl_xor_sync(0xffffffffu, s, off);
        lse_combine(m, s, m2, s2);
    }
    __shared__ float sm[8], ssum[8];
    int wid = threadIdx.x >> 5, lane = threadIdx.x & 31;
    if (lane == 0) { sm[wid] = m; ssum[wid] = s; }
    __syncthreads();
    if (threadIdx.x == 0) {
        float M = sm[0], S = ssum[0];
        #pragma unroll
        for (int i = 1; i < 8; i++) lse_combine(M, S, sm[i], ssum[i]);
        float lse = M + logf(S);
        nll[n] = lse - row[targets[n]];
    }
}

// ---------------- 8) mean-reduce loss ----------------
__global__ void loss_mean_kernel(const float* __restrict__ nll, float* __restrict__ out,
                                 long long out_size) {
    float s = 0.f;
    for (int i = threadIdx.x; i < NT; i += 256) s += nll[i];
    #pragma unroll
    for (int off = 16; off >= 1; off >>= 1) s += __shfl_xor_sync(0xffffffffu, s, off);
    __shared__ float sm[8];
    int wid = threadIdx.x >> 5, lane = threadIdx.x & 31;
    if (lane == 0) sm[wid] = s;
    __syncthreads();
    if (threadIdx.x == 0) {
        float t = 0.f;
        #pragma unroll
        for (int i = 0; i < 8; i++) t += sm[i];
        const long long NTV = (long long)NT * Vz;
        if (out_size > NTV) out[NTV] = t / (float)NT;
    }
}

// ---------------- launch ----------------
extern "C" void kernel_launch(void* const* d_in, const int* in_sizes, int n_in,
                              void* d_out, int out_size) {
    const float* idx     = (const float*)d_in[0];
    const int*   targets = (const int*)d_in[1];
    const float* W_emb   = (const float*)d_in[2];
    const float* W_attn  = (const float*)d_in[3];
    const float* W_out   = (const float*)d_in[4];
    float* out = (float*)d_out;

    void* p;
    cudaGetSymbolAddress(&p, g_embT);    float* embT  = (float*)p;
    cudaGetSymbolAddress(&p, g_x);       float* x     = (float*)p;
    cudaGetSymbolAddress(&p, g_h);       float* h     = (float*)p;
    cudaGetSymbolAddress(&p, g_qkv);     float* qkv   = (float*)p;
    cudaGetSymbolAddress(&p, g_wattn_r); float* wattn = (float*)p;
    cudaGetSymbolAddress(&p, g_wout_r);  float* wout  = (float*)p;
    cudaGetSymbolAddress(&p, g_nll);     float* nll   = (float*)p;
    cudaGetSymbolAddress(&p, g_tok);     int*   tok   = (int*)p;

    find_tokens_kernel<<<NT, 256>>>(idx, tok);
    transpose_kernel<<<dim3(Vz / 32, Dz / 32), dim3(32, 8)>>>(W_emb, embT);
    embed_kernel<<<NT, 256>>>(embT, tok, x);

    // tf32-round weights (prepass, graph-captured each replay)
    round_tf32_kernel<<<1024, 256>>>(W_attn, wattn, (long long)Lz * THREED * Dz / 4);
    round_tf32_kernel<<<1024, 256>>>(W_out, wout, (long long)Vz * Dz / 4);

    for (int l = 0; l < Lz; l++) {
        layernorm_kernel<<<NT, 256>>>(x, h);
        tf32_gemm_nt<<<dim3(THREED / BN, NT / BM), 256>>>(
            h, wattn + (size_t)l * THREED * Dz, qkv, NT, THREED, Dz);
        flash_attn_kernel<<<dim3(Tz / 64, Bz * Hz), 128>>>(qkv, x);
    }

    layernorm_kernel<<<NT, 256>>>(x, h);
    tf32_gemm_nt<<<dim3(Vz / BN, NT / BM), 256>>>(h, wout, out, NT, Vz, Dz);

    row_nll_kernel<<<NT, 256>>>(out, targets, nll);
    loss_mean_kernel<<<1, 256>>>(nll, out, (long long)out_size);
}

// round 4
// speedup vs baseline: 2.6156x; 1.4177x over previous
#include <cuda_runtime.h>
#include <cuda_bf16.h>
#include <cstdint>

// Problem constants
#define Bz 8
#define Tz 1024
#define Vz 8192
#define Dz 1024
#define Hz 16
#define HDz 64
#define Lz 6
#define NT (Bz*Tz)          // 8192 tokens
#define THREED (3*Dz)       // 3072

// ---------------- scratch (static device memory; allocation-free) ----------------
__device__ float g_embT[(size_t)Vz * Dz];       // 32 MB  W_emb transposed [V,D]
__device__ float g_x[(size_t)NT * Dz];          // 32 MB  residual stream
__device__ float g_h[(size_t)NT * Dz];          // 32 MB  layernorm output (tf32-rounded)
__device__ float g_qkv[(size_t)NT * THREED];    // 96 MB
__device__ float g_wattn_r[(size_t)Lz * THREED * Dz];  // 75 MB tf32-rounded W_attn
__device__ float g_wout_r[(size_t)Vz * Dz];     // 32 MB tf32-rounded W_out
__device__ float g_nll[NT];
__device__ int   g_tok[NT];

// cvt.rna.tf32.f32 needs a .b32 destination register
__device__ __forceinline__ float tf32_round(float x) {
    uint32_t r;
    asm("cvt.rna.tf32.f32 %0, %1;\n" : "=r"(r) : "f"(x));
    return __uint_as_float(r);
}

__device__ __forceinline__ void mma_tf32(float c[4], uint32_t a0, uint32_t a1,
                                         uint32_t a2, uint32_t a3,
                                         uint32_t b0, uint32_t b1) {
    asm volatile(
        "mma.sync.aligned.m16n8k8.row.col.f32.tf32.tf32.f32 "
        "{%0,%1,%2,%3}, {%4,%5,%6,%7}, {%8,%9}, {%0,%1,%2,%3};\n"
        : "+f"(c[0]), "+f"(c[1]), "+f"(c[2]), "+f"(c[3])
        : "r"(a0), "r"(a1), "r"(a2), "r"(a3), "r"(b0), "r"(b1));
}

// ---------------- 1) extract token ids from dense one-hot ----------------
__global__ void find_tokens_kernel(const float* __restrict__ idx, int* __restrict__ tok) {
    int n = blockIdx.x;
    const float* row = idx + (size_t)n * Vz;
    for (int i = threadIdx.x; i < Vz; i += blockDim.x) {
        if (row[i] > 0.5f) tok[n] = i;
    }
}

// ---------------- 2) transpose W_emb [D,V] -> [V,D] ----------------
__global__ void transpose_kernel(const float* __restrict__ in, float* __restrict__ out) {
    __shared__ float tile[32][33];
    int x = blockIdx.x * 32 + threadIdx.x;   // V dim
    int y0 = blockIdx.y * 32;                // D dim
    #pragma unroll
    for (int j = threadIdx.y; j < 32; j += 8)
        tile[j][threadIdx.x] = in[(size_t)(y0 + j) * Vz + x];
    __syncthreads();
    int xo = blockIdx.y * 32 + threadIdx.x;  // D dim (output inner)
    int yo0 = blockIdx.x * 32;               // V dim
    #pragma unroll
    for (int j = threadIdx.y; j < 32; j += 8)
        out[(size_t)(yo0 + j) * Dz + xo] = tile[threadIdx.x][j];
}

// ---------------- 3) embedding gather ----------------
__global__ void embed_kernel(const float* __restrict__ embT, const int* __restrict__ tok,
                             float* __restrict__ x) {
    int n = blockIdx.x;
    int t = tok[n];
    const float4* src = (const float4*)(embT + (size_t)t * Dz);
    float4* dst = (float4*)(x + (size_t)n * Dz);
    dst[threadIdx.x] = src[threadIdx.x];   // 256 threads * 4 = 1024
}

// ---------------- 3b) tf32-round a buffer (weights prepass) ----------------
__global__ void round_tf32_kernel(const float* __restrict__ in, float* __restrict__ out,
                                  long long n4) {
    long long i = (long long)blockIdx.x * blockDim.x + threadIdx.x;
    long long stride = (long long)gridDim.x * blockDim.x;
    for (; i < n4; i += stride) {
        float4 v = ((const float4*)in)[i];
        v.x = tf32_round(v.x); v.y = tf32_round(v.y);
        v.z = tf32_round(v.z); v.w = tf32_round(v.w);
        ((float4*)out)[i] = v;
    }
}

// ---------------- 4) layernorm (no affine), row of 1024, tf32-rounded output ---
__global__ void layernorm_kernel(const float* __restrict__ in, float* __restrict__ out) {
    int n = blockIdx.x;
    const float4* row = (const float4*)(in + (size_t)n * Dz);
    float4 v = row[threadIdx.x];
    float s  = v.x + v.y + v.z + v.w;
    float ss = v.x*v.x + v.y*v.y + v.z*v.z + v.w*v.w;
    #pragma unroll
    for (int off = 16; off >= 1; off >>= 1) {
        s  += __shfl_xor_sync(0xffffffffu, s,  off);
        ss += __shfl_xor_sync(0xffffffffu, ss, off);
    }
    __shared__ float sm[8], sm2[8];
    int wid = threadIdx.x >> 5, lane = threadIdx.x & 31;
    if (lane == 0) { sm[wid] = s; sm2[wid] = ss; }
    __syncthreads();
    __shared__ float s_mu, s_rstd;
    if (threadIdx.x == 0) {
        float ts = 0.f, tss = 0.f;
        #pragma unroll
        for (int i = 0; i < 8; i++) { ts += sm[i]; tss += sm2[i]; }
        float mu = ts / (float)Dz;
        float var = tss / (float)Dz - mu * mu;
        s_mu = mu;
        s_rstd = rsqrtf(var + 1e-5f);
    }
    __syncthreads();
    float mu = s_mu, rstd = s_rstd;
    float4 o;
    o.x = tf32_round((v.x - mu) * rstd); o.y = tf32_round((v.y - mu) * rstd);
    o.z = tf32_round((v.z - mu) * rstd); o.w = tf32_round((v.w - mu) * rstd);
    ((float4*)(out + (size_t)n * Dz))[threadIdx.x] = o;
}

// ---------------- 5) TF32 tensor-core GEMM NT: C[M,N] = A[M,K] * B[N,K]^T ------
#define BM 128
#define BN 128
#define BK 16
#define SST 20

__device__ __forceinline__ void cp16(uint32_t dst, const float* src) {
    asm volatile("cp.async.ca.shared.global [%0], [%1], 16;\n" :: "r"(dst), "l"(src));
}

__global__ __launch_bounds__(256)
void tf32_gemm_nt(const float* __restrict__ A, const float* __restrict__ B,
                  float* __restrict__ C, int M, int N, int K) {
    __shared__ float As[2][BM * SST];
    __shared__ float Bs[2][BN * SST];

    const int bm = blockIdx.y * BM;
    const int bn = blockIdx.x * BN;
    const int tid = threadIdx.x;
    const int wid = tid >> 5, lane = tid & 31;
    const int wm = wid >> 1;
    const int wn = wid & 1;
    const int g  = lane >> 2;
    const int tg = lane & 3;

    const int lrow = tid >> 1;
    const int lseg = (tid & 1) * 8;

    const float* Ag = A + (size_t)(bm + lrow) * K + lseg;
    const float* Bg = B + (size_t)(bn + lrow) * K + lseg;
    uint32_t AsW[2], BsW[2];
    #pragma unroll
    for (int b = 0; b < 2; b++) {
        AsW[b] = (uint32_t)__cvta_generic_to_shared(&As[b][lrow * SST + lseg]);
        BsW[b] = (uint32_t)__cvta_generic_to_shared(&Bs[b][lrow * SST + lseg]);
    }

    float c[2][8][4];
    #pragma unroll
    for (int i = 0; i < 2; i++)
        #pragma unroll
        for (int j = 0; j < 8; j++)
            #pragma unroll
            for (int r = 0; r < 4; r++) c[i][j][r] = 0.f;

    const int ntiles = K / BK;

    cp16(AsW[0],     Ag);
    cp16(AsW[0]+16,  Ag + 4);
    cp16(BsW[0],     Bg);
    cp16(BsW[0]+16,  Bg + 4);
    asm volatile("cp.async.commit_group;\n");

    for (int kt = 0; kt < ntiles; kt++) {
        const int buf = kt & 1;
        if (kt + 1 < ntiles) {
            const float* a2 = Ag + (size_t)(kt + 1) * BK;
            const float* b2 = Bg + (size_t)(kt + 1) * BK;
            cp16(AsW[buf^1],    a2);
            cp16(AsW[buf^1]+16, a2 + 4);
            cp16(BsW[buf^1],    b2);
            cp16(BsW[buf^1]+16, b2 + 4);
            asm volatile("cp.async.commit_group;\n");
            asm volatile("cp.async.wait_group 1;\n");
        } else {
            asm volatile("cp.async.wait_group 0;\n");
        }
        __syncthreads();

        const float* pA = As[buf];
        const float* pB = Bs[buf];
        #pragma unroll
        for (int ks = 0; ks < 2; ks++) {
            const int kb = ks * 8;
            uint32_t a[2][4], b[8][2];
            #pragma unroll
            for (int i = 0; i < 2; i++) {
                const int mb = wm * 32 + i * 16;
                a[i][0] = __float_as_uint(pA[(mb + g    ) * SST + kb + tg    ]);
                a[i][1] = __float_as_uint(pA[(mb + g + 8) * SST + kb + tg    ]);
                a[i][2] = __float_as_uint(pA[(mb + g    ) * SST + kb + tg + 4]);
                a[i][3] = __float_as_uint(pA[(mb + g + 8) * SST + kb + tg + 4]);
            }
            #pragma unroll
            for (int j = 0; j < 8; j++) {
                const int nb = wn * 64 + j * 8;
                b[j][0] = __float_as_uint(pB[(nb + g) * SST + kb + tg    ]);
                b[j][1] = __float_as_uint(pB[(nb + g) * SST + kb + tg + 4]);
            }
            #pragma unroll
            for (int i = 0; i < 2; i++)
                #pragma unroll
                for (int j = 0; j < 8; j++)
                    mma_tf32(c[i][j], a[i][0], a[i][1], a[i][2], a[i][3],
                             b[j][0], b[j][1]);
        }
        __syncthreads();
    }

    #pragma unroll
    for (int i = 0; i < 2; i++) {
        const int m0 = bm + wm * 32 + i * 16 + g;
        #pragma unroll
        for (int j = 0; j < 8; j++) {
            const int n0 = bn + wn * 64 + j * 8 + 2 * tg;
            float2 v0 = {c[i][j][0], c[i][j][1]};
            float2 v1 = {c[i][j][2], c[i][j][3]};
            *(float2*)(C + (size_t)m0 * N + n0)       = v0;
            *(float2*)(C + (size_t)(m0 + 8) * N + n0) = v1;
        }
    }
}

// ---------------- 6) TF32 tensor-core flash attention + residual add ----------------
// grid (T/128, B*H), 256 threads (8 warps). Q tile 128, kv tile 64, HD 64.
// Smem strides: Q/K/P 68 (A/B frag reads conflict-free), V 72 (B frag conflict-free).
#define QT 128
#define KT 64
#define QS_STRIDE 68
#define VS_STRIDE 72
#define FA_SMEM_FLOATS (QT*QS_STRIDE + KT*QS_STRIDE + QT*QS_STRIDE + KT*VS_STRIDE)
#define FA_SMEM_BYTES (FA_SMEM_FLOATS * 4)

__global__ __launch_bounds__(256)
void flash_attn_tc(const float* __restrict__ qkv, float* __restrict__ x) {
    extern __shared__ float smem[];
    float* Qs = smem;                          // [128][68]
    float* Ks = Qs + QT * QS_STRIDE;           // [64][68]
    float* Ps = Ks + KT * QS_STRIDE;           // [128][68]
    float* Vs = Ps + QT * QS_STRIDE;           // [64][72]

    const int q0 = blockIdx.x * QT;
    const int bh = blockIdx.y;
    const int b = bh >> 4, h = bh & 15;
    const float* base = qkv + (size_t)b * Tz * THREED;
    const int hc = h * HDz;

    const int tid = threadIdx.x;
    const int wid = tid >> 5, lane = tid & 31;
    const int g = lane >> 2, tg = lane & 3;
    const int m0 = wid * 16;

    // load Q tile (tf32-rounded, pre-scaled by 1/sqrt(HD))
    {
        const int r = tid >> 4;
        const int c = (tid & 15) * 4;
        #pragma unroll
        for (int rr = r; rr < QT; rr += 16) {
            float4 v = *(const float4*)(base + (size_t)(q0 + rr) * THREED + hc + c);
            v.x = tf32_round(v.x * 0.125f); v.y = tf32_round(v.y * 0.125f);
            v.z = tf32_round(v.z * 0.125f); v.w = tf32_round(v.w * 0.125f);
            *(float4*)&Qs[rr * QS_STRIDE + c] = v;
        }
    }

    float m_[2] = {-1e30f, -1e30f};
    float l_[2] = {0.f, 0.f};
    float o_acc[8][4];
    #pragma unroll
    for (int nt = 0; nt < 8; nt++)
        #pragma unroll
        for (int r = 0; r < 4; r++) o_acc[nt][r] = 0.f;

    const int nkv = (q0 + QT) >> 6;
    for (int j = 0; j < nkv; j++) {
        const int k0 = j * KT;
        __syncthreads();   // previous-iteration consumers done
        {
            const int r = tid >> 4;
            const int c = (tid & 15) * 4;
            #pragma unroll
            for (int rr = r; rr < KT; rr += 16) {
                const float* kr = base + (size_t)(k0 + rr) * THREED;
                float4 kk = *(const float4*)(kr + Dz + hc + c);
                kk.x = tf32_round(kk.x); kk.y = tf32_round(kk.y);
                kk.z = tf32_round(kk.z); kk.w = tf32_round(kk.w);
                *(float4*)&Ks[rr * QS_STRIDE + c] = kk;
                float4 vv = *(const float4*)(kr + 2 * Dz + hc + c);
                vv.x = tf32_round(vv.x); vv.y = tf32_round(vv.y);
                vv.z = tf32_round(vv.z); vv.w = tf32_round(vv.w);
                *(float4*)&Vs[rr * VS_STRIDE + c] = vv;
            }
        }
        __syncthreads();

        const bool active = (q0 + m0 + 15 >= k0);
        if (active) {
            // S = Q * K^T  (16x64 slab per warp)
            float s_acc[8][4];
            #pragma unroll
            for (int nt = 0; nt < 8; nt++)
                #pragma unroll
                for (int r = 0; r < 4; r++) s_acc[nt][r] = 0.f;

            #pragma unroll
            for (int kt = 0; kt < 8; kt++) {
                const int kb = kt * 8;
                uint32_t a0 = __float_as_uint(Qs[(m0 + g    ) * QS_STRIDE + kb + tg    ]);
                uint32_t a1 = __float_as_uint(Qs[(m0 + g + 8) * QS_STRIDE + kb + tg    ]);
                uint32_t a2 = __float_as_uint(Qs[(m0 + g    ) * QS_STRIDE + kb + tg + 4]);
                uint32_t a3 = __float_as_uint(Qs[(m0 + g + 8) * QS_STRIDE + kb + tg + 4]);
                #pragma unroll
                for (int nt = 0; nt < 8; nt++) {
                    uint32_t b0 = __float_as_uint(Ks[(nt * 8 + g) * QS_STRIDE + kb + tg    ]);
                    uint32_t b1 = __float_as_uint(Ks[(nt * 8 + g) * QS_STRIDE + kb + tg + 4]);
                    mma_tf32(s_acc[nt], a0, a1, a2, a3, b0, b1);
                }
            }

            // causal mask (diagonal tiles only)
            if (k0 + KT - 1 > q0 + m0) {
                const int r0 = q0 + m0 + g;
                const int r1 = r0 + 8;
                #pragma unroll
                for (int nt = 0; nt < 8; nt++) {
                    const int cg = k0 + nt * 8 + 2 * tg;
                    if (cg     > r0) s_acc[nt][0] = -1e30f;
                    if (cg + 1 > r0) s_acc[nt][1] = -1e30f;
                    if (cg     > r1) s_acc[nt][2] = -1e30f;
                    if (cg + 1 > r1) s_acc[nt][3] = -1e30f;
                }
            }

            // online softmax (rows g and g+8; row spread over quad lanes)
            float rmax0 = -1e30f, rmax1 = -1e30f;
            #pragma unroll
            for (int nt = 0; nt < 8; nt++) {
                rmax0 = fmaxf(rmax0, fmaxf(s_acc[nt][0], s_acc[nt][1]));
                rmax1 = fmaxf(rmax1, fmaxf(s_acc[nt][2], s_acc[nt][3]));
            }
            rmax0 = fmaxf(rmax0, __shfl_xor_sync(0xffffffffu, rmax0, 1));
            rmax0 = fmaxf(rmax0, __shfl_xor_sync(0xffffffffu, rmax0, 2));
            rmax1 = fmaxf(rmax1, __shfl_xor_sync(0xffffffffu, rmax1, 1));
            rmax1 = fmaxf(rmax1, __shfl_xor_sync(0xffffffffu, rmax1, 2));

            const float mn0 = fmaxf(m_[0], rmax0);
            const float mn1 = fmaxf(m_[1], rmax1);
            const float sc0 = __expf(m_[0] - mn0);
            const float sc1 = __expf(m_[1] - mn1);
            m_[0] = mn0; m_[1] = mn1;

            float rs0 = 0.f, rs1 = 0.f;
            #pragma unroll
            for (int nt = 0; nt < 8; nt++) {
                float p0 = __expf(s_acc[nt][0] - mn0);
                float p1 = __expf(s_acc[nt][1] - mn0);
                float p2 = __expf(s_acc[nt][2] - mn1);
                float p3 = __expf(s_acc[nt][3] - mn1);
                rs0 += p0 + p1;
                rs1 += p2 + p3;
                float2 w0 = {tf32_round(p0), tf32_round(p1)};
                float2 w1 = {tf32_round(p2), tf32_round(p3)};
                *(float2*)&Ps[(m0 + g    ) * QS_STRIDE + nt * 8 + 2 * tg] = w0;
                *(float2*)&Ps[(m0 + g + 8) * QS_STRIDE + nt * 8 + 2 * tg] = w1;
            }
            rs0 += __shfl_xor_sync(0xffffffffu, rs0, 1);
            rs0 += __shfl_xor_sync(0xffffffffu, rs0, 2);
            rs1 += __shfl_xor_sync(0xffffffffu, rs1, 1);
            rs1 += __shfl_xor_sync(0xffffffffu, rs1, 2);
            l_[0] = l_[0] * sc0 + rs0;
            l_[1] = l_[1] * sc1 + rs1;

            #pragma unroll
            for (int nt = 0; nt < 8; nt++) {
                o_acc[nt][0] *= sc0; o_acc[nt][1] *= sc0;
                o_acc[nt][2] *= sc1; o_acc[nt][3] *= sc1;
            }
            __syncwarp();

            // O += P * V   (P slab is warp-private)
            #pragma unroll
            for (int kt = 0; kt < 8; kt++) {
                const int kb = kt * 8;
                uint32_t a0 = __float_as_uint(Ps[(m0 + g    ) * QS_STRIDE + kb + tg    ]);
                uint32_t a1 = __float_as_uint(Ps[(m0 + g + 8) * QS_STRIDE + kb + tg    ]);
                uint32_t a2 = __float_as_uint(Ps[(m0 + g    ) * QS_STRIDE + kb + tg + 4]);
                uint32_t a3 = __float_as_uint(Ps[(m0 + g + 8) * QS_STRIDE + kb + tg + 4]);
                #pragma unroll
                for (int nt = 0; nt < 8; nt++) {
                    uint32_t b0 = __float_as_uint(Vs[(kb + tg    ) * VS_STRIDE + nt * 8 + g]);
                    uint32_t b1 = __float_as_uint(Vs[(kb + tg + 4) * VS_STRIDE + nt * 8 + g]);
                    mma_tf32(o_acc[nt], a0, a1, a2, a3, b0, b1);
                }
            }
        }
    }

    // epilogue: normalize + residual add
    const float inv0 = 1.0f / l_[0];
    const float inv1 = 1.0f / l_[1];
    const int r0 = b * Tz + q0 + m0 + g;
    #pragma unroll
    for (int nt = 0; nt < 8; nt++) {
        float* xp0 = x + (size_t)r0 * Dz + hc + nt * 8 + 2 * tg;
        float* xp1 = xp0 + 8 * Dz;
        float2 v0 = *(float2*)xp0;
        float2 v1 = *(float2*)xp1;
        v0.x += o_acc[nt][0] * inv0; v0.y += o_acc[nt][1] * inv0;
        v1.x += o_acc[nt][2] * inv1; v1.y += o_acc[nt][3] * inv1;
        *(float2*)xp0 = v0;
        *(float2*)xp1 = v1;
    }
}

// ---------------- 7) per-row NLL: lse(row) - row[target] ----------------
__device__ __forceinline__ void lse_combine(float& m, float& s, float m2, float s2) {
    float M = fmaxf(m, m2);
    s = s * __expf(m - M) + s2 * __expf(m2 - M);
    m = M;
}
__global__ void row_nll_kernel(const float* __restrict__ logits, const int* __restrict__ targets,
                               float* __restrict__ nll) {
    int n = blockIdx.x;
    const float* row = logits + (size_t)n * Vz;
    float m = -1e30f, s = 0.f;
    for (int i = threadIdx.x; i < Vz; i += 256) {
        float v = row[i];
        float M = fmaxf(m, v);
        s = s * __expf(m - M) + __expf(v - M);
        m = M;
    }
    #pragma unroll
    for (int off = 16; off >= 1; off >>= 1) {
        float m2 = __shfl_xor_sync(0xffffffffu, m, off);
        float s2 = __shfl_xor_sync(0xffffffffu, s, off);
        lse_combine(m, s, m2, s2);
    }
    __shared__ float sm[8], ssum[8];
    int wid = threadIdx.x >> 5, lane = threadIdx.x & 31;
    if (lane == 0) { sm[wid] = m; ssum[wid] = s; }
    __syncthreads();
    if (threadIdx.x == 0) {
        float M = sm[0], S = ssum[0];
        #pragma unroll
        for (int i = 1; i < 8; i++) lse_combine(M, S, sm[i], ssum[i]);
        float lse = M + logf(S);
        nll[n] = lse - row[targets[n]];
    }
}

// ---------------- 8) mean-reduce loss ----------------
__global__ void loss_mean_kernel(const float* __restrict__ nll, float* __restrict__ out,
                                 long long out_size) {
    float s = 0.f;
    for (int i = threadIdx.x; i < NT; i += 256) s += nll[i];
    #pragma unroll
    for (int off = 16; off >= 1; off >>= 1) s += __shfl_xor_sync(0xffffffffu, s, off);
    __shared__ float sm[8];
    int wid = threadIdx.x >> 5, lane = threadIdx.x & 31;
    if (lane == 0) sm[wid] = s;
    __syncthreads();
    if (threadIdx.x == 0) {
        float t = 0.f;
        #pragma unroll
        for (int i = 0; i < 8; i++) t += sm[i];
        const long long NTV = (long long)NT * Vz;
        if (out_size > NTV) out[NTV] = t / (float)NT;
    }
}

// ---------------- launch ----------------
extern "C" void kernel_launch(void* const* d_in, const int* in_sizes, int n_in,
                              void* d_out, int out_size) {
    const float* idx     = (const float*)d_in[0];
    const int*   targets = (const int*)d_in[1];
    const float* W_emb   = (const float*)d_in[2];
    const float* W_attn  = (const float*)d_in[3];
    const float* W_out   = (const float*)d_in[4];
    float* out = (float*)d_out;

    void* p;
    cudaGetSymbolAddress(&p, g_embT);    float* embT  = (float*)p;
    cudaGetSymbolAddress(&p, g_x);       float* x     = (float*)p;
    cudaGetSymbolAddress(&p, g_h);       float* h     = (float*)p;
    cudaGetSymbolAddress(&p, g_qkv);     float* qkv   = (float*)p;
    cudaGetSymbolAddress(&p, g_wattn_r); float* wattn = (float*)p;
    cudaGetSymbolAddress(&p, g_wout_r);  float* wout  = (float*)p;
    cudaGetSymbolAddress(&p, g_nll);     float* nll   = (float*)p;
    cudaGetSymbolAddress(&p, g_tok);     int*   tok   = (int*)p;

    cudaFuncSetAttribute(flash_attn_tc,
                         cudaFuncAttributeMaxDynamicSharedMemorySize, FA_SMEM_BYTES);

    find_tokens_kernel<<<NT, 256>>>(idx, tok);
    transpose_kernel<<<dim3(Vz / 32, Dz / 32), dim3(32, 8)>>>(W_emb, embT);
    embed_kernel<<<NT, 256>>>(embT, tok, x);

    round_tf32_kernel<<<1024, 256>>>(W_attn, wattn, (long long)Lz * THREED * Dz / 4);
    round_tf32_kernel<<<1024, 256>>>(W_out, wout, (long long)Vz * Dz / 4);

    for (int l = 0; l < Lz; l++) {
        layernorm_kernel<<<NT, 256>>>(x, h);
        tf32_gemm_nt<<<dim3(THREED / BN, NT / BM), 256>>>(
            h, wattn + (size_t)l * THREED * Dz, qkv, NT, THREED, Dz);
        flash_attn_tc<<<dim3(Tz / QT, Bz * Hz), 256, FA_SMEM_BYTES>>>(qkv, x);
    }

    layernorm_kernel<<<NT, 256>>>(x, h);
    tf32_gemm_nt<<<dim3(Vz / BN, NT / BM), 256>>>(h, wout, out, NT, Vz, Dz);

    row_nll_kernel<<<NT, 256>>>(out, targets, nll);
    loss_mean_kernel<<<1, 256>>>(nll, out, (long long)out_size);
}

// round 5
// speedup vs baseline: 4.8887x; 1.8691x over previous
#include <cuda_runtime.h>
#include <cuda_fp16.h>
#include <cstdint>

// Problem constants
#define Bz 8
#define Tz 1024
#define Vz 8192
#define Dz 1024
#define Hz 16
#define HDz 64
#define Lz 6
#define NT (Bz*Tz)          // 8192 tokens
#define THREED (3*Dz)       // 3072

// ---------------- scratch (static device memory; allocation-free) ----------------
__device__ float  g_embT[(size_t)Vz * Dz];          // 32 MB  W_emb transposed [V,D]
__device__ float  g_x[(size_t)NT * Dz];             // 32 MB  residual stream
__device__ __half g_hh[(size_t)NT * Dz];            // 16 MB  layernorm output (half)
__device__ __half g_qkvh[(size_t)NT * THREED];      // 48 MB  qkv (half)
__device__ __half g_wattn_h[(size_t)Lz * THREED * Dz];  // 36 MB
__device__ __half g_wout_h[(size_t)Vz * Dz];        // 16 MB
__device__ float  g_nll[NT];
__device__ int    g_tok[NT];

__device__ __forceinline__ uint32_t h2u(__half2 v) { return *(uint32_t*)&v; }

__device__ __forceinline__ void mma_f16(float c[4], uint32_t a0, uint32_t a1,
                                        uint32_t a2, uint32_t a3,
                                        uint32_t b0, uint32_t b1) {
    asm volatile(
        "mma.sync.aligned.m16n8k16.row.col.f32.f16.f16.f32 "
        "{%0,%1,%2,%3}, {%4,%5,%6,%7}, {%8,%9}, {%0,%1,%2,%3};\n"
        : "+f"(c[0]), "+f"(c[1]), "+f"(c[2]), "+f"(c[3])
        : "r"(a0), "r"(a1), "r"(a2), "r"(a3), "r"(b0), "r"(b1));
}

// ---------------- 1) extract token ids from dense one-hot ----------------
__global__ void find_tokens_kernel(const float* __restrict__ idx, int* __restrict__ tok) {
    int n = blockIdx.x;
    const float* row = idx + (size_t)n * Vz;
    for (int i = threadIdx.x; i < Vz; i += blockDim.x) {
        if (row[i] > 0.5f) tok[n] = i;
    }
}

// ---------------- 2) transpose W_emb [D,V] -> [V,D] ----------------
__global__ void transpose_kernel(const float* __restrict__ in, float* __restrict__ out) {
    __shared__ float tile[32][33];
    int x = blockIdx.x * 32 + threadIdx.x;
    int y0 = blockIdx.y * 32;
    #pragma unroll
    for (int j = threadIdx.y; j < 32; j += 8)
        tile[j][threadIdx.x] = in[(size_t)(y0 + j) * Vz + x];
    __syncthreads();
    int xo = blockIdx.y * 32 + threadIdx.x;
    int yo0 = blockIdx.x * 32;
    #pragma unroll
    for (int j = threadIdx.y; j < 32; j += 8)
        out[(size_t)(yo0 + j) * Dz + xo] = tile[threadIdx.x][j];
}

// ---------------- 3) embedding gather ----------------
__global__ void embed_kernel(const float* __restrict__ embT, const int* __restrict__ tok,
                             float* __restrict__ x) {
    int n = blockIdx.x;
    int t = tok[n];
    const float4* src = (const float4*)(embT + (size_t)t * Dz);
    float4* dst = (float4*)(x + (size_t)n * Dz);
    dst[threadIdx.x] = src[threadIdx.x];
}

// ---------------- 3b) f32 -> half conversion (weights prepass) ----------------
__global__ void f32_to_h_kernel(const float* __restrict__ in, __half* __restrict__ out,
                                long long n4) {
    long long i = (long long)blockIdx.x * blockDim.x + threadIdx.x;
    long long stride = (long long)gridDim.x * blockDim.x;
    for (; i < n4; i += stride) {
        float4 v = ((const float4*)in)[i];
        uint2 o;
        o.x = h2u(__floats2half2_rn(v.x, v.y));
        o.y = h2u(__floats2half2_rn(v.z, v.w));
        ((uint2*)out)[i] = o;
    }
}

// ---------------- 4) layernorm (no affine), row 1024, half output ----------------
__global__ void layernorm_h_kernel(const float* __restrict__ in, __half* __restrict__ out) {
    int n = blockIdx.x;
    const float4* row = (const float4*)(in + (size_t)n * Dz);
    float4 v = row[threadIdx.x];
    float s  = v.x + v.y + v.z + v.w;
    float ss = v.x*v.x + v.y*v.y + v.z*v.z + v.w*v.w;
    #pragma unroll
    for (int off = 16; off >= 1; off >>= 1) {
        s  += __shfl_xor_sync(0xffffffffu, s,  off);
        ss += __shfl_xor_sync(0xffffffffu, ss, off);
    }
    __shared__ float sm[8], sm2[8];
    int wid = threadIdx.x >> 5, lane = threadIdx.x & 31;
    if (lane == 0) { sm[wid] = s; sm2[wid] = ss; }
    __syncthreads();
    __shared__ float s_mu, s_rstd;
    if (threadIdx.x == 0) {
        float ts = 0.f, tss = 0.f;
        #pragma unroll
        for (int i = 0; i < 8; i++) { ts += sm[i]; tss += sm2[i]; }
        float mu = ts / (float)Dz;
        float var = tss / (float)Dz - mu * mu;
        s_mu = mu;
        s_rstd = rsqrtf(var + 1e-5f);
    }
    __syncthreads();
    float mu = s_mu, rstd = s_rstd;
    uint2 o;
    o.x = h2u(__floats2half2_rn((v.x - mu) * rstd, (v.y - mu) * rstd));
    o.y = h2u(__floats2half2_rn((v.z - mu) * rstd, (v.w - mu) * rstd));
    ((uint2*)(out + (size_t)n * Dz))[threadIdx.x] = o;
}

// ---------------- 5) FP16 tensor-core GEMM NT: C[M,N] = A[M,K] * B[N,K]^T ------
// CTA 128x128x32, 8 warps (4x2), warp tile 32x64, double-buffered cp.async.
#define BM 128
#define BN 128
#define BK 32
#define SWH 40   // smem row stride in halves (20 words) -> conflict-free frag reads

__device__ __forceinline__ void cp16(uint32_t dst, const void* src) {
    asm volatile("cp.async.ca.shared.global [%0], [%1], 16;\n" :: "r"(dst), "l"(src));
}

template <bool HALF_OUT>
__global__ __launch_bounds__(256)
void h_gemm_nt(const __half* __restrict__ A, const __half* __restrict__ B,
               void* __restrict__ Cv, int M, int N, int K) {
    __shared__ __half As[2][BM * SWH];
    __shared__ __half Bs[2][BN * SWH];

    const int bm = blockIdx.y * BM;
    const int bn = blockIdx.x * BN;
    const int tid = threadIdx.x;
    const int wid = tid >> 5, lane = tid & 31;
    const int wm = wid >> 1;
    const int wn = wid & 1;
    const int g  = lane >> 2;
    const int tg = lane & 3;

    const int lrow = tid >> 1;         // 0..127
    const int lseg = (tid & 1) * 16;   // halves: 0 or 16

    const __half* Ag = A + (size_t)(bm + lrow) * K + lseg;
    const __half* Bg = B + (size_t)(bn + lrow) * K + lseg;
    uint32_t AsW[2], BsW[2];
    #pragma unroll
    for (int b = 0; b < 2; b++) {
        AsW[b] = (uint32_t)__cvta_generic_to_shared(&As[b][lrow * SWH + lseg]);
        BsW[b] = (uint32_t)__cvta_generic_to_shared(&Bs[b][lrow * SWH + lseg]);
    }

    float c[2][8][4];
    #pragma unroll
    for (int i = 0; i < 2; i++)
        #pragma unroll
        for (int j = 0; j < 8; j++)
            #pragma unroll
            for (int r = 0; r < 4; r++) c[i][j][r] = 0.f;

    const int ntiles = K / BK;

    cp16(AsW[0],      Ag);
    cp16(AsW[0] + 16, Ag + 8);
    cp16(BsW[0],      Bg);
    cp16(BsW[0] + 16, Bg + 8);
    asm volatile("cp.async.commit_group;\n");

    for (int kt = 0; kt < ntiles; kt++) {
        const int buf = kt & 1;
        if (kt + 1 < ntiles) {
            const __half* a2 = Ag + (size_t)(kt + 1) * BK;
            const __half* b2 = Bg + (size_t)(kt + 1) * BK;
            cp16(AsW[buf^1],      a2);
            cp16(AsW[buf^1] + 16, a2 + 8);
            cp16(BsW[buf^1],      b2);
            cp16(BsW[buf^1] + 16, b2 + 8);
            asm volatile("cp.async.commit_group;\n");
            asm volatile("cp.async.wait_group 1;\n");
        } else {
            asm volatile("cp.async.wait_group 0;\n");
        }
        __syncthreads();

        const uint32_t* pA = (const uint32_t*)As[buf];
        const uint32_t* pB = (const uint32_t*)Bs[buf];
        #pragma unroll
        for (int ks = 0; ks < 2; ks++) {
            const int kw = ks * 8;   // word offset within row
            uint32_t a[2][4], b[8][2];
            #pragma unroll
            for (int i = 0; i < 2; i++) {
                const int mb = wm * 32 + i * 16;
                a[i][0] = pA[(mb + g    ) * 20 + kw + tg    ];
                a[i][1] = pA[(mb + g + 8) * 20 + kw + tg    ];
                a[i][2] = pA[(mb + g    ) * 20 + kw + tg + 4];
                a[i][3] = pA[(mb + g + 8) * 20 + kw + tg + 4];
            }
            #pragma unroll
            for (int j = 0; j < 8; j++) {
                const int nb = wn * 64 + j * 8;
                b[j][0] = pB[(nb + g) * 20 + kw + tg    ];
                b[j][1] = pB[(nb + g) * 20 + kw + tg + 4];
            }
            #pragma unroll
            for (int i = 0; i < 2; i++)
                #pragma unroll
                for (int j = 0; j < 8; j++)
                    mma_f16(c[i][j], a[i][0], a[i][1], a[i][2], a[i][3],
                            b[j][0], b[j][1]);
        }
        __syncthreads();
    }

    #pragma unroll
    for (int i = 0; i < 2; i++) {
        const int m0 = bm + wm * 32 + i * 16 + g;
        #pragma unroll
        for (int j = 0; j < 8; j++) {
            const int n0 = bn + wn * 64 + j * 8 + 2 * tg;
            if (HALF_OUT) {
                __half* Ch = (__half*)Cv;
                *(__half2*)(Ch + (size_t)m0 * N + n0) =
                    __floats2half2_rn(c[i][j][0], c[i][j][1]);
                *(__half2*)(Ch + (size_t)(m0 + 8) * N + n0) =
                    __floats2half2_rn(c[i][j][2], c[i][j][3]);
            } else {
                float* Cf = (float*)Cv;
                float2 v0 = {c[i][j][0], c[i][j][1]};
                float2 v1 = {c[i][j][2], c[i][j][3]};
                *(float2*)(Cf + (size_t)m0 * N + n0)       = v0;
                *(float2*)(Cf + (size_t)(m0 + 8) * N + n0) = v1;
            }
        }
    }
}

// ---------------- 6) FP16 tensor-core flash attention + residual add ----------------
// grid (T/128, B*H), 256 threads (8 warps), each warp one 16-row slab.
// Qs/Ks: half rows stride 72 halves (36 words). Vt: half2-pair words [rp=32][stride 72 words].
#define QT 128
#define KT 64
#define QSW 36
#define VSW 72

__global__ __launch_bounds__(256)
void flash_attn_h(const __half* __restrict__ qkv, float* __restrict__ x) {
    __shared__ uint32_t Qs[QT * QSW];   // 18432 B
    __shared__ uint32_t Ks[KT * QSW];   //  9216 B
    __shared__ uint32_t Vt[32 * VSW];   //  9216 B

    const int q0 = blockIdx.x * QT;
    const int bh = blockIdx.y;
    const int b = bh >> 4, h = bh & 15;
    const __half* base = qkv + (size_t)b * Tz * THREED;
    const int hc = h * HDz;

    const int tid = threadIdx.x;
    const int wid = tid >> 5, lane = tid & 31;
    const int g = lane >> 2, tg = lane & 3;
    const int m0 = wid * 16;

    // load Q tile (half, pre-scaled by 1/sqrt(HD)=0.125 — exact in fp16)
    {
        const int r = tid >> 1;
        const int cw = (tid & 1) * 16;
        const uint4* src = (const uint4*)(base + (size_t)(q0 + r) * THREED + hc) + (tid & 1) * 4;
        const __half2 sc = __float2half2_rn(0.125f);
        #pragma unroll
        for (int i = 0; i < 4; i++) {
            uint4 v = src[i];
            __half2* pv = (__half2*)&v;
            pv[0] = __hmul2(pv[0], sc); pv[1] = __hmul2(pv[1], sc);
            pv[2] = __hmul2(pv[2], sc); pv[3] = __hmul2(pv[3], sc);
            *(uint4*)&Qs[r * QSW + cw + i * 4] = v;
        }
    }
    __syncthreads();

    // hoist Q fragments into registers (reused across all kv tiles)
    uint32_t qf[4][4];
    #pragma unroll
    for (int kt = 0; kt < 4; kt++) {
        qf[kt][0] = Qs[(m0 + g    ) * QSW + kt * 8 + tg    ];
        qf[kt][1] = Qs[(m0 + g + 8) * QSW + kt * 8 + tg    ];
        qf[kt][2] = Qs[(m0 + g    ) * QSW + kt * 8 + tg + 4];
        qf[kt][3] = Qs[(m0 + g + 8) * QSW + kt * 8 + tg + 4];
    }

    float m_[2] = {-1e30f, -1e30f};
    float l_[2] = {0.f, 0.f};
    float o_acc[8][4];
    #pragma unroll
    for (int nt = 0; nt < 8; nt++)
        #pragma unroll
        for (int r = 0; r < 4; r++) o_acc[nt][r] = 0.f;

    const int nkv = (q0 + QT) >> 6;
    for (int j = 0; j < nkv; j++) {
        const int k0 = j * KT;
        __syncthreads();   // previous-iteration consumers done
        // K tile: rows half, stride QSW words
        {
            const int r = tid >> 2, cw = (tid & 3) * 8;
            const uint4* src = (const uint4*)(base + (size_t)(k0 + r) * THREED + Dz + hc) + (tid & 3) * 2;
            *(uint4*)&Ks[r * QSW + cw]     = src[0];
            *(uint4*)&Ks[r * QSW + cw + 4] = src[1];
        }
        // V tile transposed into half2-pair words: Vt[rp][c] = {V[2rp][c], V[2rp+1][c]}
        {
            const int c = tid & 63, rp0 = tid >> 6;
            const __half* vb = base + 2 * Dz + hc + c;
            #pragma unroll
            for (int i = 0; i < 8; i++) {
                const int rp = rp0 + i * 4;
                uint32_t lo = __half_as_ushort(vb[(size_t)(k0 + 2 * rp    ) * THREED]);
                uint32_t hi = __half_as_ushort(vb[(size_t)(k0 + 2 * rp + 1) * THREED]);
                Vt[rp * VSW + c] = lo | (hi << 16);
            }
        }
        __syncthreads();

        if (q0 + m0 + 15 >= k0) {
            // S = Q K^T (16x64 per warp), fp32 accum
            float s_acc[8][4];
            #pragma unroll
            for (int nt = 0; nt < 8; nt++)
                #pragma unroll
                for (int r = 0; r < 4; r++) s_acc[nt][r] = 0.f;
            #pragma unroll
            for (int kt = 0; kt < 4; kt++) {
                #pragma unroll
                for (int nt = 0; nt < 8; nt++) {
                    uint32_t b0 = Ks[(nt * 8 + g) * QSW + kt * 8 + tg    ];
                    uint32_t b1 = Ks[(nt * 8 + g) * QSW + kt * 8 + tg + 4];
                    mma_f16(s_acc[nt], qf[kt][0], qf[kt][1], qf[kt][2], qf[kt][3], b0, b1);
                }
            }

            // causal mask (diagonal tiles only)
            if (k0 + KT - 1 > q0 + m0) {
                const int r0 = q0 + m0 + g;
                const int r1 = r0 + 8;
                #pragma unroll
                for (int nt = 0; nt < 8; nt++) {
                    const int cg = k0 + nt * 8 + 2 * tg;
                    if (cg     > r0) s_acc[nt][0] = -1e30f;
                    if (cg + 1 > r0) s_acc[nt][1] = -1e30f;
                    if (cg     > r1) s_acc[nt][2] = -1e30f;
                    if (cg + 1 > r1) s_acc[nt][3] = -1e30f;
                }
            }

            // online softmax; P packed straight into fp16 A-fragments (no smem)
            float rmax0 = -1e30f, rmax1 = -1e30f;
            #pragma unroll
            for (int nt = 0; nt < 8; nt++) {
                rmax0 = fmaxf(rmax0, fmaxf(s_acc[nt][0], s_acc[nt][1]));
                rmax1 = fmaxf(rmax1, fmaxf(s_acc[nt][2], s_acc[nt][3]));
            }
            rmax0 = fmaxf(rmax0, __shfl_xor_sync(0xffffffffu, rmax0, 1));
            rmax0 = fmaxf(rmax0, __shfl_xor_sync(0xffffffffu, rmax0, 2));
            rmax1 = fmaxf(rmax1, __shfl_xor_sync(0xffffffffu, rmax1, 1));
            rmax1 = fmaxf(rmax1, __shfl_xor_sync(0xffffffffu, rmax1, 2));

            const float mn0 = fmaxf(m_[0], rmax0);
            const float mn1 = fmaxf(m_[1], rmax1);
            const float sc0 = __expf(m_[0] - mn0);
            const float sc1 = __expf(m_[1] - mn1);
            m_[0] = mn0; m_[1] = mn1;

            uint32_t pf[4][4];
            float rs0 = 0.f, rs1 = 0.f;
            #pragma unroll
            for (int nt = 0; nt < 8; nt++) {
                float p0 = __expf(s_acc[nt][0] - mn0);
                float p1 = __expf(s_acc[nt][1] - mn0);
                float p2 = __expf(s_acc[nt][2] - mn1);
                float p3 = __expf(s_acc[nt][3] - mn1);
                rs0 += p0 + p1;
                rs1 += p2 + p3;
                pf[nt >> 1][(nt & 1) * 2 + 0] = h2u(__floats2half2_rn(p0, p1));
                pf[nt >> 1][(nt & 1) * 2 + 1] = h2u(__floats2half2_rn(p2, p3));
            }
            rs0 += __shfl_xor_sync(0xffffffffu, rs0, 1);
            rs0 += __shfl_xor_sync(0xffffffffu, rs0, 2);
            rs1 += __shfl_xor_sync(0xffffffffu, rs1, 1);
            rs1 += __shfl_xor_sync(0xffffffffu, rs1, 2);
            l_[0] = l_[0] * sc0 + rs0;
            l_[1] = l_[1] * sc1 + rs1;

            #pragma unroll
            for (int nt = 0; nt < 8; nt++) {
                o_acc[nt][0] *= sc0; o_acc[nt][1] *= sc0;
                o_acc[nt][2] *= sc1; o_acc[nt][3] *= sc1;
            }

            // O += P V
            #pragma unroll
            for (int kt = 0; kt < 4; kt++) {
                #pragma unroll
                for (int nt = 0; nt < 8; nt++) {
                    uint32_t b0 = Vt[(kt * 8 + tg    ) * VSW + nt * 8 + g];
                    uint32_t b1 = Vt[(kt * 8 + tg + 4) * VSW + nt * 8 + g];
                    mma_f16(o_acc[nt], pf[kt][0], pf[kt][1], pf[kt][2], pf[kt][3], b0, b1);
                }
            }
        }
    }

    // epilogue: normalize + residual add into x (f32)
    const float inv0 = 1.0f / l_[0];
    const float inv1 = 1.0f / l_[1];
    const int r0 = b * Tz + q0 + m0 + g;
    #pragma unroll
    for (int nt = 0; nt < 8; nt++) {
        float* xp0 = x + (size_t)r0 * Dz + hc + nt * 8 + 2 * tg;
        float* xp1 = xp0 + 8 * Dz;
        float2 v0 = *(float2*)xp0;
        float2 v1 = *(float2*)xp1;
        v0.x += o_acc[nt][0] * inv0; v0.y += o_acc[nt][1] * inv0;
        v1.x += o_acc[nt][2] * inv1; v1.y += o_acc[nt][3] * inv1;
        *(float2*)xp0 = v0;
        *(float2*)xp1 = v1;
    }
}

// ---------------- 7) per-row NLL: lse(row) - row[target] ----------------
__device__ __forceinline__ void lse_combine(float& m, float& s, float m2, float s2) {
    float M = fmaxf(m, m2);
    s = s * __expf(m - M) + s2 * __expf(m2 - M);
    m = M;
}
__global__ void row_nll_kernel(const float* __restrict__ logits, const int* __restrict__ targets,
                               float* __restrict__ nll) {
    int n = blockIdx.x;
    const float* row = logits + (size_t)n * Vz;
    float m = -1e30f, s = 0.f;
    for (int i = threadIdx.x; i < Vz; i += 256) {
        float v = row[i];
        float M = fmaxf(m, v);
        s = s * __expf(m - M) + __expf(v - M);
        m = M;
    }
    #pragma unroll
    for (int off = 16; off >= 1; off >>= 1) {
        float m2 = __shfl_xor_sync(0xffffffffu, m, off);
        float s2 = __shfl_xor_sync(0xffffffffu, s, off);
        lse_combine(m, s, m2, s2);
    }
    __shared__ float sm[8], ssum[8];
    int wid = threadIdx.x >> 5, lane = threadIdx.x & 31;
    if (lane == 0) { sm[wid] = m; ssum[wid] = s; }
    __syncthreads();
    if (threadIdx.x == 0) {
        float M = sm[0], S = ssum[0];
        #pragma unroll
        for (int i = 1; i < 8; i++) lse_combine(M, S, sm[i], ssum[i]);
        float lse = M + logf(S);
        nll[n] = lse - row[targets[n]];
    }
}

// ---------------- 8) mean-reduce loss ----------------
__global__ void loss_mean_kernel(const float* __restrict__ nll, float* __restrict__ out,
                                 long long out_size) {
    float s = 0.f;
    for (int i = threadIdx.x; i < NT; i += 256) s += nll[i];
    #pragma unroll
    for (int off = 16; off >= 1; off >>= 1) s += __shfl_xor_sync(0xffffffffu, s, off);
    __shared__ float sm[8];
    int wid = threadIdx.x >> 5, lane = threadIdx.x & 31;
    if (lane == 0) sm[wid] = s;
    __syncthreads();
    if (threadIdx.x == 0) {
        float t = 0.f;
        #pragma unroll
        for (int i = 0; i < 8; i++) t += sm[i];
        const long long NTV = (long long)NT * Vz;
        if (out_size > NTV) out[NTV] = t / (float)NT;
    }
}

// ---------------- launch ----------------
extern "C" void kernel_launch(void* const* d_in, const int* in_sizes, int n_in,
                              void* d_out, int out_size) {
    const float* idx     = (const float*)d_in[0];
    const int*   targets = (const int*)d_in[1];
    const float* W_emb   = (const float*)d_in[2];
    const float* W_attn  = (const float*)d_in[3];
    const float* W_out   = (const float*)d_in[4];
    float* out = (float*)d_out;

    void* p;
    cudaGetSymbolAddress(&p, g_embT);    float*  embT  = (float*)p;
    cudaGetSymbolAddress(&p, g_x);       float*  x     = (float*)p;
    cudaGetSymbolAddress(&p, g_hh);      __half* hh    = (__half*)p;
    cudaGetSymbolAddress(&p, g_qkvh);    __half* qkvh  = (__half*)p;
    cudaGetSymbolAddress(&p, g_wattn_h); __half* wattn = (__half*)p;
    cudaGetSymbolAddress(&p, g_wout_h);  __half* wout  = (__half*)p;
    cudaGetSymbolAddress(&p, g_nll);     float*  nll   = (float*)p;
    cudaGetSymbolAddress(&p, g_tok);     int*    tok   = (int*)p;

    find_tokens_kernel<<<NT, 256>>>(idx, tok);
    transpose_kernel<<<dim3(Vz / 32, Dz / 32), dim3(32, 8)>>>(W_emb, embT);
    embed_kernel<<<NT, 256>>>(embT, tok, x);

    // weight conversion prepass (f32 -> half)
    f32_to_h_kernel<<<1024, 256>>>(W_attn, wattn, (long long)Lz * THREED * Dz / 4);
    f32_to_h_kernel<<<1024, 256>>>(W_out, wout, (long long)Vz * Dz / 4);

    for (int l = 0; l < Lz; l++) {
        layernorm_h_kernel<<<NT, 256>>>(x, hh);
        h_gemm_nt<true><<<dim3(THREED / BN, NT / BM), 256>>>(
            hh, wattn + (size_t)l * THREED * Dz, qkvh, NT, THREED, Dz);
        flash_attn_h<<<dim3(Tz / QT, Bz * Hz), 256>>>(qkvh, x);
    }

    layernorm_h_kernel<<<NT, 256>>>(x, hh);
    h_gemm_nt<false><<<dim3(Vz / BN, NT / BM), 256>>>(hh, wout, out, NT, Vz, Dz);

    row_nll_kernel<<<NT, 256>>>(out, targets, nll);
    loss_mean_kernel<<<1, 256>>>(nll, out, (long long)out_size);
}

// round 7
// speedup vs baseline: 6.0390x; 1.2353x over previous
#include <cuda_runtime.h>
#include <cuda_fp16.h>
#include <cstdint>

// Problem constants
#define Bz 8
#define Tz 1024
#define Vz 8192
#define Dz 1024
#define Hz 16
#define HDz 64
#define Lz 6
#define NT (Bz*Tz)          // 8192 tokens
#define THREED (3*Dz)       // 3072

// ---------------- scratch (static device memory; allocation-free) ----------------
__device__ float  g_embT[(size_t)Vz * Dz];
__device__ float  g_x[(size_t)NT * Dz];
__device__ __half g_hh[(size_t)NT * Dz];
__device__ __half g_qkvh[(size_t)NT * THREED];
__device__ __half g_wattn_h[(size_t)Lz * THREED * Dz];
__device__ __half g_wout_h[(size_t)Vz * Dz];
__device__ float  g_nll[NT];
__device__ int    g_tok[NT];

__device__ __forceinline__ uint32_t h2u(__half2 v) { return *(uint32_t*)&v; }

__device__ __forceinline__ void mma_f16(float c[4], uint32_t a0, uint32_t a1,
                                        uint32_t a2, uint32_t a3,
                                        uint32_t b0, uint32_t b1) {
    asm volatile(
        "mma.sync.aligned.m16n8k16.row.col.f32.f16.f16.f32 "
        "{%0,%1,%2,%3}, {%4,%5,%6,%7}, {%8,%9}, {%0,%1,%2,%3};\n"
        : "+f"(c[0]), "+f"(c[1]), "+f"(c[2]), "+f"(c[3])
        : "r"(a0), "r"(a1), "r"(a2), "r"(a3), "r"(b0), "r"(b1));
}

__device__ __forceinline__ void ldsm4(uint32_t& r0, uint32_t& r1, uint32_t& r2,
                                      uint32_t& r3, uint32_t a) {
    asm volatile("ldmatrix.sync.aligned.m8n8.x4.shared.b16 {%0,%1,%2,%3}, [%4];"
                 : "=r"(r0), "=r"(r1), "=r"(r2), "=r"(r3) : "r"(a));
}
__device__ __forceinline__ void ldsm4t(uint32_t& r0, uint32_t& r1, uint32_t& r2,
                                       uint32_t& r3, uint32_t a) {
    asm volatile("ldmatrix.sync.aligned.m8n8.x4.trans.shared.b16 {%0,%1,%2,%3}, [%4];"
                 : "=r"(r0), "=r"(r1), "=r"(r2), "=r"(r3) : "r"(a));
}
__device__ __forceinline__ void cp16(uint32_t dst, const void* src) {
    asm volatile("cp.async.ca.shared.global [%0], [%1], 16;\n" :: "r"(dst), "l"(src));
}

// ---------------- 1) extract token ids from dense one-hot ----------------
__global__ void find_tokens_kernel(const float* __restrict__ idx, int* __restrict__ tok) {
    int n = blockIdx.x;
    const float* row = idx + (size_t)n * Vz;
    for (int i = threadIdx.x; i < Vz; i += blockDim.x) {
        if (row[i] > 0.5f) tok[n] = i;
    }
}

// ---------------- 2) transpose W_emb [D,V] -> [V,D] ----------------
__global__ void transpose_kernel(const float* __restrict__ in, float* __restrict__ out) {
    __shared__ float tile[32][33];
    int x = blockIdx.x * 32 + threadIdx.x;
    int y0 = blockIdx.y * 32;
    #pragma unroll
    for (int j = threadIdx.y; j < 32; j += 8)
        tile[j][threadIdx.x] = in[(size_t)(y0 + j) * Vz + x];
    __syncthreads();
    int xo = blockIdx.y * 32 + threadIdx.x;
    int yo0 = blockIdx.x * 32;
    #pragma unroll
    for (int j = threadIdx.y; j < 32; j += 8)
        out[(size_t)(yo0 + j) * Dz + xo] = tile[threadIdx.x][j];
}

// ---------------- 3) embedding gather ----------------
__global__ void embed_kernel(const float* __restrict__ embT, const int* __restrict__ tok,
                             float* __restrict__ x) {
    int n = blockIdx.x;
    int t = tok[n];
    const float4* src = (const float4*)(embT + (size_t)t * Dz);
    float4* dst = (float4*)(x + (size_t)n * Dz);
    dst[threadIdx.x] = src[threadIdx.x];
}

// ---------------- 3b) f32 -> half conversion (weights prepass) ----------------
__global__ void f32_to_h_kernel(const float* __restrict__ in, __half* __restrict__ out,
                                long long n4) {
    long long i = (long long)blockIdx.x * blockDim.x + threadIdx.x;
    long long stride = (long long)gridDim.x * blockDim.x;
    for (; i < n4; i += stride) {
        float4 v = ((const float4*)in)[i];
        uint2 o;
        o.x = h2u(__floats2half2_rn(v.x, v.y));
        o.y = h2u(__floats2half2_rn(v.z, v.w));
        ((uint2*)out)[i] = o;
    }
}

// ---------------- 4) layernorm (no affine), row 1024, half output ----------------
__global__ void layernorm_h_kernel(const float* __restrict__ in, __half* __restrict__ out) {
    int n = blockIdx.x;
    const float4* row = (const float4*)(in + (size_t)n * Dz);
    float4 v = row[threadIdx.x];
    float s  = v.x + v.y + v.z + v.w;
    float ss = v.x*v.x + v.y*v.y + v.z*v.z + v.w*v.w;
    #pragma unroll
    for (int off = 16; off >= 1; off >>= 1) {
        s  += __shfl_xor_sync(0xffffffffu, s,  off);
        ss += __shfl_xor_sync(0xffffffffu, ss, off);
    }
    __shared__ float sm[8], sm2[8];
    int wid = threadIdx.x >> 5, lane = threadIdx.x & 31;
    if (lane == 0) { sm[wid] = s; sm2[wid] = ss; }
    __syncthreads();
    __shared__ float s_mu, s_rstd;
    if (threadIdx.x == 0) {
        float ts = 0.f, tss = 0.f;
        #pragma unroll
        for (int i = 0; i < 8; i++) { ts += sm[i]; tss += sm2[i]; }
        float mu = ts / (float)Dz;
        float var = tss / (float)Dz - mu * mu;
        s_mu = mu;
        s_rstd = rsqrtf(var + 1e-5f);
    }
    __syncthreads();
    float mu = s_mu, rstd = s_rstd;
    uint2 o;
    o.x = h2u(__floats2half2_rn((v.x - mu) * rstd, (v.y - mu) * rstd));
    o.y = h2u(__floats2half2_rn((v.z - mu) * rstd, (v.w - mu) * rstd));
    ((uint2*)(out + (size_t)n * Dz))[threadIdx.x] = o;
}

// ---------------- 5) FP16 GEMM NT, ldmatrix + 3-stage cp.async pipeline ---------
// C[M,N] = A[M,K] * B[N,K]^T. CTA 128x128x32, 8 warps (4x2), warp 32x64.
#define BM 128
#define BN 128
#define BK 32
#define SWH 40          // halves per smem row (32 + 8 pad) -> conflict-free ldmatrix
#define GSTAGE_H (BM * SWH)          // halves per stage per matrix
#define GEMM_SMEM_BYTES (3 * GSTAGE_H * 2 * 2)   // 61440

template <bool HALF_OUT>
__global__ __launch_bounds__(256)
void h_gemm_nt(const __half* __restrict__ A, const __half* __restrict__ B,
               void* __restrict__ Cv, int M, int N, int K) {
    extern __shared__ __half gsm[];
    __half* As = gsm;
    __half* Bs = gsm + 3 * GSTAGE_H;

    const int bm = blockIdx.y * BM;
    const int bn = blockIdx.x * BN;
    const int tid = threadIdx.x;
    const int wid = tid >> 5, lane = tid & 31;
    const int wm = wid >> 1;
    const int wn = wid & 1;
    const int g  = lane >> 2;
    const int tg = lane & 3;

    const int lrow = tid >> 1;
    const int lseg = (tid & 1) * 16;

    const __half* Ag = A + (size_t)(bm + lrow) * K + lseg;
    const __half* Bg = B + (size_t)(bn + lrow) * K + lseg;
    const uint32_t AsB = (uint32_t)__cvta_generic_to_shared(As);
    const uint32_t BsB = (uint32_t)__cvta_generic_to_shared(Bs);
    const uint32_t stageB = GSTAGE_H * 2;          // bytes per stage
    const uint32_t aDst = AsB + (lrow * SWH + lseg) * 2;
    const uint32_t bDst = BsB + (lrow * SWH + lseg) * 2;

    // ldmatrix fragment base addresses
    const uint32_t aFrag = AsB + ((wm * 32 + (lane & 15)) * SWH + (lane >> 4) * 8) * 2;
    const uint32_t bFrag = BsB + ((wn * 64 + (lane & 7) + ((lane >> 4) << 3)) * SWH
                                  + ((lane >> 3) & 1) * 8) * 2;

    float c[2][8][4];
    #pragma unroll
    for (int i = 0; i < 2; i++)
        #pragma unroll
        for (int j = 0; j < 8; j++)
            #pragma unroll
            for (int r = 0; r < 4; r++) c[i][j][r] = 0.f;

    const int ntiles = K / BK;

    auto issue = [&](int kt) {
        const int s = kt % 3;
        const __half* a2 = Ag + (size_t)kt * BK;
        const __half* b2 = Bg + (size_t)kt * BK;
        const uint32_t ad = aDst + s * stageB;
        const uint32_t bd = bDst + s * stageB;
        // 16B per cp16: dst advances 16 BYTES, src advances 8 halves (FIXED)
        cp16(ad, a2); cp16(ad + 16, a2 + 8);
        cp16(bd, b2); cp16(bd + 16, b2 + 8);
        asm volatile("cp.async.commit_group;\n");
    };

    issue(0);
    issue(1);

    for (int kt = 0; kt < ntiles; kt++) {
        if (kt + 1 < ntiles) asm volatile("cp.async.wait_group 1;\n");
        else                 asm volatile("cp.async.wait_group 0;\n");
        __syncthreads();
        if (kt + 2 < ntiles) issue(kt + 2);

        const uint32_t sOff = (kt % 3) * stageB;
        #pragma unroll
        for (int ks = 0; ks < 2; ks++) {
            uint32_t a[2][4], b[8][2];
            #pragma unroll
            for (int i = 0; i < 2; i++)
                ldsm4(a[i][0], a[i][1], a[i][2], a[i][3],
                      aFrag + sOff + (i * 16 * SWH + ks * 16) * 2);
            #pragma unroll
            for (int p = 0; p < 4; p++)
                ldsm4(b[2*p][0], b[2*p][1], b[2*p+1][0], b[2*p+1][1],
                      bFrag + sOff + (p * 16 * SWH + ks * 16) * 2);
            #pragma unroll
            for (int i = 0; i < 2; i++)
                #pragma unroll
                for (int j = 0; j < 8; j++)
                    mma_f16(c[i][j], a[i][0], a[i][1], a[i][2], a[i][3],
                            b[j][0], b[j][1]);
        }
    }

    #pragma unroll
    for (int i = 0; i < 2; i++) {
        const int m0 = bm + wm * 32 + i * 16 + g;
        #pragma unroll
        for (int j = 0; j < 8; j++) {
            const int n0 = bn + wn * 64 + j * 8 + 2 * tg;
            if (HALF_OUT) {
                __half* Ch = (__half*)Cv;
                *(__half2*)(Ch + (size_t)m0 * N + n0) =
                    __floats2half2_rn(c[i][j][0], c[i][j][1]);
                *(__half2*)(Ch + (size_t)(m0 + 8) * N + n0) =
                    __floats2half2_rn(c[i][j][2], c[i][j][3]);
            } else {
                float* Cf = (float*)Cv;
                float2 v0 = {c[i][j][0], c[i][j][1]};
                float2 v1 = {c[i][j][2], c[i][j][3]};
                *(float2*)(Cf + (size_t)m0 * N + n0)       = v0;
                *(float2*)(Cf + (size_t)(m0 + 8) * N + n0) = v1;
            }
        }
    }
}

// ---------------- 6) FP16 flash attention: ldmatrix + 3-stage cp.async KV ------
// grid (T/128, B*H), 256 threads (8 warps), warp = 16-row slab.
#define QT 128
#define KT 64
#define KSW 72         // halves per smem row (64 + 8 pad) -> conflict-free ldmatrix
#define KVSTAGE_H (KT * KSW)
#define FA_SMEM_BYTES ((QT * KSW + 6 * KVSTAGE_H) * 2)   // 73728

__global__ __launch_bounds__(256)
void flash_attn_h(const __half* __restrict__ qkv, float* __restrict__ x) {
    extern __shared__ __half smp[];
    __half* Qs = smp;                        // [128][72]
    __half* Ks = smp + QT * KSW;             // 3 stages [64][72]
    __half* Vs = Ks + 3 * KVSTAGE_H;         // 3 stages [64][72]

    const int q0 = blockIdx.x * QT;
    const int bh = blockIdx.y;
    const int b = bh >> 4, h = bh & 15;
    const __half* base = qkv + (size_t)b * Tz * THREED;
    const int hc = h * HDz;

    const int tid = threadIdx.x;
    const int wid = tid >> 5, lane = tid & 31;
    const int g = lane >> 2, tg = lane & 3;
    const int m0 = wid * 16;

    const uint32_t QsB = (uint32_t)__cvta_generic_to_shared(Qs);
    const uint32_t KsB = (uint32_t)__cvta_generic_to_shared(Ks);
    const uint32_t VsB = (uint32_t)__cvta_generic_to_shared(Vs);
    const uint32_t kvStageB = KVSTAGE_H * 2;

    // load Q tile (half, pre-scaled by 0.125)
    {
        const int r = tid >> 1;
        const int ch = (tid & 1) * 32;     // halves
        const uint4* src = (const uint4*)(base + (size_t)(q0 + r) * THREED + hc + ch);
        const __half2 sc = __float2half2_rn(0.125f);
        #pragma unroll
        for (int i = 0; i < 4; i++) {
            uint4 v = src[i];
            __half2* pv = (__half2*)&v;
            pv[0] = __hmul2(pv[0], sc); pv[1] = __hmul2(pv[1], sc);
            pv[2] = __hmul2(pv[2], sc); pv[3] = __hmul2(pv[3], sc);
            *(uint4*)&Qs[r * KSW + ch + i * 8] = v;
        }
    }

    const int nkv = (q0 + QT) >> 6;

    // KV cp.async issue: rows r, r+32; one 16B segment (8 halves) per row each
    auto issueKV = [&](int j) {
        const int s = j % 3;
        const int k0 = j * KT;
        const int r = tid >> 3;
        const int seg = (tid & 7) * 8;     // halves
        const __half* krow = base + (size_t)(k0 + r) * THREED + Dz + hc + seg;
        const __half* vrow = krow + Dz;
        const uint32_t kd = KsB + s * kvStageB + (r * KSW + seg) * 2;
        const uint32_t vd = VsB + s * kvStageB + (r * KSW + seg) * 2;
        cp16(kd, krow);
        cp16(vd, vrow);
        cp16(kd + 32 * KSW * 2, krow + (size_t)32 * THREED);
        cp16(vd + 32 * KSW * 2, vrow + (size_t)32 * THREED);
        asm volatile("cp.async.commit_group;\n");
    };

    issueKV(0);
    if (nkv > 1) issueKV(1);
    __syncthreads();   // Q tile visible

    // hoist Q fragments (A-frag: row = m0+(lane&15), col = kt*16 + (lane>>4)*8)
    uint32_t qf[4][4];
    {
        const uint32_t qAddr = QsB + ((m0 + (lane & 15)) * KSW + (lane >> 4) * 8) * 2;
        #pragma unroll
        for (int kt = 0; kt < 4; kt++)
            ldsm4(qf[kt][0], qf[kt][1], qf[kt][2], qf[kt][3], qAddr + kt * 32);
    }

    // fragment bases
    const uint32_t kFrag = KsB + (((lane & 7) + ((lane >> 4) << 3)) * KSW
                                  + ((lane >> 3) & 1) * 8) * 2;
    const uint32_t vFrag = VsB + ((lane & 15) * KSW + (lane >> 4) * 8) * 2;

    float m_[2] = {-1e30f, -1e30f};
    float l_[2] = {0.f, 0.f};
    float o_acc[8][4];
    #pragma unroll
    for (int nt = 0; nt < 8; nt++)
        #pragma unroll
        for (int r = 0; r < 4; r++) o_acc[nt][r] = 0.f;

    for (int j = 0; j < nkv; j++) {
        const int k0 = j * KT;
        if (j + 1 < nkv) asm volatile("cp.async.wait_group 1;\n");
        else             asm volatile("cp.async.wait_group 0;\n");
        __syncthreads();
        if (j + 2 < nkv) issueKV(j + 2);

        if (q0 + m0 + 15 >= k0) {
            const uint32_t sOff = (j % 3) * kvStageB;

            // S = Q K^T
            float s_acc[8][4];
            #pragma unroll
            for (int nt = 0; nt < 8; nt++)
                #pragma unroll
                for (int r = 0; r < 4; r++) s_acc[nt][r] = 0.f;
            #pragma unroll
            for (int kt = 0; kt < 4; kt++) {
                uint32_t bk[8][2];
                #pragma unroll
                for (int p = 0; p < 4; p++)
                    ldsm4(bk[2*p][0], bk[2*p][1], bk[2*p+1][0], bk[2*p+1][1],
                          kFrag + sOff + (p * 16 * KSW + kt * 16) * 2);
                #pragma unroll
                for (int nt = 0; nt < 8; nt++)
                    mma_f16(s_acc[nt], qf[kt][0], qf[kt][1], qf[kt][2], qf[kt][3],
                            bk[nt][0], bk[nt][1]);
            }

            // causal mask (diagonal tiles only)
            if (k0 + KT - 1 > q0 + m0) {
                const int r0 = q0 + m0 + g;
                const int r1 = r0 + 8;
                #pragma unroll
                for (int nt = 0; nt < 8; nt++) {
                    const int cg = k0 + nt * 8 + 2 * tg;
                    if (cg     > r0) s_acc[nt][0] = -1e30f;
                    if (cg + 1 > r0) s_acc[nt][1] = -1e30f;
                    if (cg     > r1) s_acc[nt][2] = -1e30f;
                    if (cg + 1 > r1) s_acc[nt][3] = -1e30f;
                }
            }

            // online softmax; P packed into fp16 A-fragments (registers only)
            float rmax0 = -1e30f, rmax1 = -1e30f;
            #pragma unroll
            for (int nt = 0; nt < 8; nt++) {
                rmax0 = fmaxf(rmax0, fmaxf(s_acc[nt][0], s_acc[nt][1]));
                rmax1 = fmaxf(rmax1, fmaxf(s_acc[nt][2], s_acc[nt][3]));
            }
            rmax0 = fmaxf(rmax0, __shfl_xor_sync(0xffffffffu, rmax0, 1));
            rmax0 = fmaxf(rmax0, __shfl_xor_sync(0xffffffffu, rmax0, 2));
            rmax1 = fmaxf(rmax1, __shfl_xor_sync(0xffffffffu, rmax1, 1));
            rmax1 = fmaxf(rmax1, __shfl_xor_sync(0xffffffffu, rmax1, 2));

            const float mn0 = fmaxf(m_[0], rmax0);
            const float mn1 = fmaxf(m_[1], rmax1);
            const float sc0 = __expf(m_[0] - mn0);
            const float sc1 = __expf(m_[1] - mn1);
            m_[0] = mn0; m_[1] = mn1;

            uint32_t pf[4][4];
            float rs0 = 0.f, rs1 = 0.f;
            #pragma unroll
            for (int nt = 0; nt < 8; nt++) {
                float p0 = __expf(s_acc[nt][0] - mn0);
                float p1 = __expf(s_acc[nt][1] - mn0);
                float p2 = __expf(s_acc[nt][2] - mn1);
                float p3 = __expf(s_acc[nt][3] - mn1);
                rs0 += p0 + p1;
                rs1 += p2 + p3;
                pf[nt >> 1][(nt & 1) * 2 + 0] = h2u(__floats2half2_rn(p0, p1));
                pf[nt >> 1][(nt & 1) * 2 + 1] = h2u(__floats2half2_rn(p2, p3));
            }
            rs0 += __shfl_xor_sync(0xffffffffu, rs0, 1);
            rs0 += __shfl_xor_sync(0xffffffffu, rs0, 2);
            rs1 += __shfl_xor_sync(0xffffffffu, rs1, 1);
            rs1 += __shfl_xor_sync(0xffffffffu, rs1, 2);
            l_[0] = l_[0] * sc0 + rs0;
            l_[1] = l_[1] * sc1 + rs1;

            #pragma unroll
            for (int nt = 0; nt < 8; nt++) {
                o_acc[nt][0] *= sc0; o_acc[nt][1] *= sc0;
                o_acc[nt][2] *= sc1; o_acc[nt][3] *= sc1;
            }

            // O += P V   (V fragments via ldmatrix.trans from row-major smem)
            #pragma unroll
            for (int kt = 0; kt < 4; kt++) {
                uint32_t bv[8][2];
                #pragma unroll
                for (int p = 0; p < 4; p++)
                    ldsm4t(bv[2*p][0], bv[2*p][1], bv[2*p+1][0], bv[2*p+1][1],
                           vFrag + sOff + (kt * 16 * KSW + p * 16) * 2);
                #pragma unroll
                for (int nt = 0; nt < 8; nt++)
                    mma_f16(o_acc[nt], pf[kt][0], pf[kt][1], pf[kt][2], pf[kt][3],
                            bv[nt][0], bv[nt][1]);
            }
        }
    }

    // epilogue: normalize + residual add into x (f32)
    const float inv0 = 1.0f / l_[0];
    const float inv1 = 1.0f / l_[1];
    const int r0 = b * Tz + q0 + m0 + g;
    #pragma unroll
    for (int nt = 0; nt < 8; nt++) {
        float* xp0 = x + (size_t)r0 * Dz + hc + nt * 8 + 2 * tg;
        float* xp1 = xp0 + 8 * Dz;
        float2 v0 = *(float2*)xp0;
        float2 v1 = *(float2*)xp1;
        v0.x += o_acc[nt][0] * inv0; v0.y += o_acc[nt][1] * inv0;
        v1.x += o_acc[nt][2] * inv1; v1.y += o_acc[nt][3] * inv1;
        *(float2*)xp0 = v0;
        *(float2*)xp1 = v1;
    }
}

// ---------------- 7) per-row NLL: lse(row) - row[target] ----------------
__device__ __forceinline__ void lse_combine(float& m, float& s, float m2, float s2) {
    float M = fmaxf(m, m2);
    s = s * __expf(m - M) + s2 * __expf(m2 - M);
    m = M;
}
__global__ void row_nll_kernel(const float* __restrict__ logits, const int* __restrict__ targets,
                               float* __restrict__ nll) {
    int n = blockIdx.x;
    const float* row = logits + (size_t)n * Vz;
    float m = -1e30f, s = 0.f;
    for (int i = threadIdx.x; i < Vz; i += 256) {
        float v = row[i];
        float M = fmaxf(m, v);
        s = s * __expf(m - M) + __expf(v - M);
        m = M;
    }
    #pragma unroll
    for (int off = 16; off >= 1; off >>= 1) {
        float m2 = __shfl_xor_sync(0xffffffffu, m, off);
        float s2 = __shfl_xor_sync(0xffffffffu, s, off);
        lse_combine(m, s, m2, s2);
    }
    __shared__ float sm[8], ssum[8];
    int wid = threadIdx.x >> 5, lane = threadIdx.x & 31;
    if (lane == 0) { sm[wid] = m; ssum[wid] = s; }
    __syncthreads();
    if (threadIdx.x == 0) {
        float M = sm[0], S = ssum[0];
        #pragma unroll
        for (int i = 1; i < 8; i++) lse_combine(M, S, sm[i], ssum[i]);
        float lse = M + logf(S);
        nll[n] = lse - row[targets[n]];
    }
}

// ---------------- 8) mean-reduce loss ----------------
__global__ void loss_mean_kernel(const float* __restrict__ nll, float* __restrict__ out,
                                 long long out_size) {
    float s = 0.f;
    for (int i = threadIdx.x; i < NT; i += 256) s += nll[i];
    #pragma unroll
    for (int off = 16; off >= 1; off >>= 1) s += __shfl_xor_sync(0xffffffffu, s, off);
    __shared__ float sm[8];
    int wid = threadIdx.x >> 5, lane = threadIdx.x & 31;
    if (lane == 0) sm[wid] = s;
    __syncthreads();
    if (threadIdx.x == 0) {
        float t = 0.f;
        #pragma unroll
        for (int i = 0; i < 8; i++) t += sm[i];
        const long long NTV = (long long)NT * Vz;
        if (out_size > NTV) out[NTV] = t / (float)NT;
    }
}

// ---------------- launch ----------------
extern "C" void kernel_launch(void* const* d_in, const int* in_sizes, int n_in,
                              void* d_out, int out_size) {
    const float* idx     = (const float*)d_in[0];
    const int*   targets = (const int*)d_in[1];
    const float* W_emb   = (const float*)d_in[2];
    const float* W_attn  = (const float*)d_in[3];
    const float* W_out   = (const float*)d_in[4];
    float* out = (float*)d_out;

    void* p;
    cudaGetSymbolAddress(&p, g_embT);    float*  embT  = (float*)p;
    cudaGetSymbolAddress(&p, g_x);       float*  x     = (float*)p;
    cudaGetSymbolAddress(&p, g_hh);      __half* hh    = (__half*)p;
    cudaGetSymbolAddress(&p, g_qkvh);    __half* qkvh  = (__half*)p;
    cudaGetSymbolAddress(&p, g_wattn_h); __half* wattn = (__half*)p;
    cudaGetSymbolAddress(&p, g_wout_h);  __half* wout  = (__half*)p;
    cudaGetSymbolAddress(&p, g_nll);     float*  nll   = (float*)p;
    cudaGetSymbolAddress(&p, g_tok);     int*    tok   = (int*)p;

    cudaFuncSetAttribute(h_gemm_nt<true>,
                         cudaFuncAttributeMaxDynamicSharedMemorySize, GEMM_SMEM_BYTES);
    cudaFuncSetAttribute(h_gemm_nt<false>,
                         cudaFuncAttributeMaxDynamicSharedMemorySize, GEMM_SMEM_BYTES);
    cudaFuncSetAttribute(flash_attn_h,
                         cudaFuncAttributeMaxDynamicSharedMemorySize, FA_SMEM_BYTES);

    find_tokens_kernel<<<NT, 256>>>(idx, tok);
    transpose_kernel<<<dim3(Vz / 32, Dz / 32), dim3(32, 8)>>>(W_emb, embT);
    embed_kernel<<<NT, 256>>>(embT, tok, x);

    f32_to_h_kernel<<<1024, 256>>>(W_attn, wattn, (long long)Lz * THREED * Dz / 4);
    f32_to_h_kernel<<<1024, 256>>>(W_out, wout, (long long)Vz * Dz / 4);

    for (int l = 0; l < Lz; l++) {
        layernorm_h_kernel<<<NT, 256>>>(x, hh);
        h_gemm_nt<true><<<dim3(THREED / BN, NT / BM), 256, GEMM_SMEM_BYTES>>>(
            hh, wattn + (size_t)l * THREED * Dz, qkvh, NT, THREED, Dz);
        flash_attn_h<<<dim3(Tz / QT, Bz * Hz), 256, FA_SMEM_BYTES>>>(qkvh, x);
    }

    layernorm_h_kernel<<<NT, 256>>>(x, hh);
    h_gemm_nt<false><<<dim3(Vz / BN, NT / BM), 256, GEMM_SMEM_BYTES>>>(hh, wout, out, NT, Vz, Dz);

    row_nll_kernel<<<NT, 256>>>(out, targets, nll);
    loss_mean_kernel<<<1, 256>>>(nll, out, (long long)out_size);
}